// round 5
// baseline (speedup 1.0000x reference)
#include <cuda_runtime.h>
#include <cuda_bf16.h>
#include <mma.h>
#include <cstdint>

using namespace nvcuda;

#define NTOK 4096
#define DIM 256
#define NHEAD 8
#define HDD (NHEAD*DIM*DIM)
#define BSTRIDE 4128            // padded fp32 row stride of compact bias

// ---------------- scratch (device globals; no cudaMalloc allowed) ----------------
__device__ __nv_bfloat16 g_xln [NTOK*DIM];      // compacted valid rows
__device__ __nv_bfloat16 g_wqkv[3*HDD];
__device__ __nv_bfloat16 g_wo  [DIM*NHEAD*DIM];
__device__ __nv_bfloat16 g_wff [DIM*DIM];
__device__ __nv_bfloat16 g_qkv [3ULL*NHEAD*NTOK*DIM];    // compacted rows per head
__device__ __nv_bfloat16 g_cat [(size_t)NTOK*NHEAD*DIM]; // valid rows written; masked zfilled at Wo load
__device__ float         g_xout[NTOK*DIM];
__device__ __nv_bfloat16 g_xln2[NTOK*DIM];
__device__ float         g_bias[(size_t)NTOK*BSTRIDE];   // compact (spatial+edge)
__device__ int           g_nvalid;
__device__ int           g_idx [NTOK];          // compacted -> original token id
__device__ int           g_cidx[NTOK];          // original -> compacted (or -1)

// ---------------- cp.async helpers ----------------
__device__ __forceinline__ void cp16(void* dst, const void* src) {
    uint32_t d = (uint32_t)__cvta_generic_to_shared(dst);
    asm volatile("cp.async.cg.shared.global [%0], [%1], 16;\n" :: "r"(d), "l"(src));
}
__device__ __forceinline__ void cp16p(void* dst, const void* src, bool p) {
    uint32_t d = (uint32_t)__cvta_generic_to_shared(dst);
    int sz = p ? 16 : 0;
    asm volatile("cp.async.cg.shared.global [%0], [%1], 16, %2;\n" :: "r"(d), "l"(src), "r"(sz));
}
__device__ __forceinline__ void cp_commit() {
    asm volatile("cp.async.commit_group;\n");
}
__device__ __forceinline__ void cp_wait0() {
    asm volatile("cp.async.wait_group 0;\n");
}

// ---------------- mask compaction: prefix scan over 4096 mask values -------------
__global__ void compact_kernel(const int* __restrict__ mask)
{
    __shared__ int warpsum[32];
    int t = threadIdx.x;              // 1024 threads, 4 elems each
    int base = t * 4;
    int m[4], s = 0;
    #pragma unroll
    for (int i = 0; i < 4; i++) { m[i] = (mask[base+i] != 0); s += m[i]; }
    int lane = t & 31, w = t >> 5;
    int pre = s;
    #pragma unroll
    for (int o = 1; o < 32; o <<= 1) {
        int v = __shfl_up_sync(0xffffffffu, pre, o);
        if (lane >= o) pre += v;
    }
    if (lane == 31) warpsum[w] = pre;
    __syncthreads();
    if (t < 32) {
        int v = warpsum[t];
        #pragma unroll
        for (int o = 1; o < 32; o <<= 1) {
            int u = __shfl_up_sync(0xffffffffu, v, o);
            if (t >= o) v += u;
        }
        warpsum[t] = v;
    }
    __syncthreads();
    int off = pre - s + ((w > 0) ? warpsum[w-1] : 0);
    #pragma unroll
    for (int i = 0; i < 4; i++) {
        if (m[i]) { g_idx[off] = base + i; g_cidx[base+i] = off; off++; }
        else      { g_cidx[base+i] = -1; }
    }
    if (t == 0) g_nvalid = warpsum[31];
}

// ---------------- fused weight conversion fp32 -> bf16 ----------------
__global__ void cvt_all_kernel(const float* __restrict__ Wq, const float* __restrict__ Wk,
                               const float* __restrict__ Wv, const float* __restrict__ Wo,
                               const float* __restrict__ Wff)
{
    int i = blockIdx.x * 256 + threadIdx.x;
    if      (i <   HDD) g_wqkv[i] = __float2bfloat16(Wq[i]);
    else if (i < 2*HDD) g_wqkv[i] = __float2bfloat16(Wk[i -   HDD]);
    else if (i < 3*HDD) g_wqkv[i] = __float2bfloat16(Wv[i - 2*HDD]);
    else if (i < 4*HDD) g_wo [i - 3*HDD] = __float2bfloat16(Wo [i - 3*HDD]);
    else                g_wff[i - 4*HDD] = __float2bfloat16(Wff[i - 4*HDD]);
}

// ---------------- layernorm: fp32 in -> bf16 out (optionally compacted) ----------
template<int COMPACT>
__global__ void ln_kernel(const float* __restrict__ x, const float* __restrict__ g,
                          const float* __restrict__ b, __nv_bfloat16* __restrict__ out)
{
    int row = blockIdx.x;
    int orow = row;
    if (COMPACT) { orow = g_cidx[row]; if (orow < 0) return; }
    int t = threadIdx.x;
    float v = x[row*DIM + t];
    float sum = v, sq = v*v;
    #pragma unroll
    for (int o = 16; o > 0; o >>= 1) {
        sum += __shfl_xor_sync(0xffffffffu, sum, o);
        sq  += __shfl_xor_sync(0xffffffffu, sq,  o);
    }
    __shared__ float s1[8], s2[8];
    if ((t & 31) == 0) { s1[t>>5] = sum; s2[t>>5] = sq; }
    __syncthreads();
    __shared__ float smu, srstd;
    if (t == 0) {
        float S = 0.f, Q = 0.f;
        #pragma unroll
        for (int i = 0; i < 8; i++) { S += s1[i]; Q += s2[i]; }
        float m = S * (1.0f/DIM);
        smu = m;
        srstd = rsqrtf(Q * (1.0f/DIM) - m*m + 1e-5f);
    }
    __syncthreads();
    out[orow*DIM + t] = __float2bfloat16((v - smu) * srstd * g[t] + b[t]);
}

// ---------------- compact bias precompute: g_bias[i,j] = sp[gi,gj]+ed[gi,gj] -----
__global__ void bias_pre_kernel(const float* __restrict__ spatial,
                                const float* __restrict__ edge)
{
    int i = blockIdx.y;
    if (i >= g_nvalid) return;
    int j = blockIdx.x * 256 + threadIdx.x;
    if (j >= g_nvalid) return;
    int gi = g_idx[i];
    int gj = __ldg(&g_idx[j]);
    size_t off = (size_t)gi*NTOK + gj;
    g_bias[(size_t)i*BSTRIDE + j] = __ldg(&spatial[off]) + __ldg(&edge[off]);
}

// ---------------- 128x128 bf16 WMMA GEMM, 64-wide K panels, cp.async 2-stage -----
// C = A @ B^T.  EPI 0 (+COMPACT): QKV scatter (bias + q-scale, bf16 out)
//               EPI 1: bias + residual, fp32 out.  ZMASK: zero-fill masked A rows.
#define GEMM_SMEM (4*128*72*2 > 128*132*4 ? 4*128*72*2 : 128*132*4)   // 73728

template<int EPI, int COMPACT, int ZMASK>
__global__ void gemm_kernel(const __nv_bfloat16* __restrict__ A,
                            const __nv_bfloat16* __restrict__ B,
                            int K,
                            const float* __restrict__ b0,
                            const float* __restrict__ b1,
                            const float* __restrict__ b2,
                            const float* __restrict__ res,
                            float* __restrict__ outf,
                            __nv_bfloat16* __restrict__ outb)
{
    int bm = blockIdx.x * 128;
    if (COMPACT && bm >= g_nvalid) return;

    extern __shared__ char smem[];
    __nv_bfloat16* As = (__nv_bfloat16*)smem;          // 2 stages [128][72]
    __nv_bfloat16* Bs = As + 2*128*72;                 // 2 stages [128][72]
    float* Cs = (float*)smem;                          // [128][132] alias

    int bn = blockIdx.y * 128;
    int t = threadIdx.x;
    int w = t >> 5;
    int wr = w & 3, wc = w >> 2;   // 4x2 warp grid, each warp 32x64

    // per-thread chunk rows (constant over panels): id = t + k*256, row=id>>3
    bool pm[4];
    #pragma unroll
    for (int k = 0; k < 4; k++) {
        int r = (t + k*256) >> 3;
        pm[k] = !ZMASK || (g_cidx[bm + r] >= 0);
    }

    wmma::fragment<wmma::accumulator,16,16,16,float> acc[2][4];
    #pragma unroll
    for (int i = 0; i < 2; i++)
        #pragma unroll
        for (int j = 0; j < 4; j++)
            wmma::fill_fragment(acc[i][j], 0.0f);

    int nP = K >> 6;

    auto prefetch = [&](int p, int st) {
        const __nv_bfloat16* Ap = A + (size_t)bm*K + p*64;
        const __nv_bfloat16* Bp = B + (size_t)bn*K + p*64;
        __nv_bfloat16* Ad = As + st*128*72;
        __nv_bfloat16* Bd = Bs + st*128*72;
        #pragma unroll
        for (int k = 0; k < 4; k++) {
            int id = t + k*256;
            int r = id >> 3, c = (id & 7) << 3;
            cp16p(Ad + r*72 + c, Ap + (size_t)r*K + c, pm[k]);
            cp16 (Bd + r*72 + c, Bp + (size_t)r*K + c);
        }
        cp_commit();
    };

    prefetch(0, 0);
    for (int p = 0; p < nP; p++) {
        cp_wait0();
        __syncthreads();
        if (p + 1 < nP) prefetch(p + 1, (p + 1) & 1);
        int st = p & 1;
        __nv_bfloat16* Ad = As + st*128*72;
        __nv_bfloat16* Bd = Bs + st*128*72;
        #pragma unroll
        for (int kk = 0; kk < 4; kk++) {
            wmma::fragment<wmma::matrix_a,16,16,16,__nv_bfloat16,wmma::row_major> af[2];
            #pragma unroll
            for (int i = 0; i < 2; i++)
                wmma::load_matrix_sync(af[i], Ad + (wr*32 + i*16)*72 + kk*16, 72);
            #pragma unroll
            for (int j = 0; j < 4; j++) {
                wmma::fragment<wmma::matrix_b,16,16,16,__nv_bfloat16,wmma::col_major> bfr;
                wmma::load_matrix_sync(bfr, Bd + (wc*64 + j*16)*72 + kk*16, 72);
                #pragma unroll
                for (int i = 0; i < 2; i++)
                    wmma::mma_sync(acc[i][j], af[i], bfr, acc[i][j]);
            }
        }
        __syncthreads();
    }

    #pragma unroll
    for (int i = 0; i < 2; i++)
        #pragma unroll
        for (int j = 0; j < 4; j++)
            wmma::store_matrix_sync(&Cs[(wr*32 + i*16)*132 + wc*64 + j*16], acc[i][j],
                                    132, wmma::mem_row_major);
    __syncthreads();

    for (int idx = t; idx < 128*128; idx += 256) {
        int r = idx >> 7, c = idx & 127;
        int n = bm + r, cc = bn + c;
        float v = Cs[r*132 + c];
        if (EPI == 0) {
            int which = cc >> 11;               // 0=q, 1=k, 2=v
            const float* bp = (which == 0) ? b0 : (which == 1) ? b1 : b2;
            v += bp[cc & 2047];
            if (which == 0) v *= 0.0625f;       // 1/sqrt(D), D=256
            int h = (cc >> 8) & 7;
            int e = cc & 255;
            outb[((size_t)which*NHEAD + h)*NTOK*DIM + (size_t)n*DIM + e] = __float2bfloat16(v);
        } else {
            v += b0[cc] + res[(size_t)n*DIM + cc];
            outf[(size_t)n*DIM + cc] = v;
        }
    }
}

// ---------------- fused biased attention, compacted, cp.async 2-stage pipeline ---
// grid: (NHEAD, NTOK/64). Each block: 64 compacted query rows of one head.
// dyn smem layout (bytes):
//  Qs [64][264] bf16     @ 0       33792
//  Ks 2x[64][264] bf16   @ 33792   67584   (epilogue alias: Os [64][260] f32)
//  Vs 2x[64][264] bf16   @ 101376  67584
//  Bs 2x[64][68]  f32    @ 168960  34816
//  Sb [64][72]    f32    @ 203776  18432
//  Ps [64][72]    bf16   @ 222208   9216
//  rg [64] int           @ 231424    256
//  linv [64] f32         @ 231680    256      total 231936
#define ATT_SMEM 231936
#define QS 264

__global__ void attn_kernel()
{
    int Nv = g_nvalid;
    int n0 = blockIdx.y * 64;
    if (n0 >= Nv) return;

    extern __shared__ char smem[];
    __nv_bfloat16* Qs = (__nv_bfloat16*)smem;
    __nv_bfloat16* Ks = (__nv_bfloat16*)(smem + 33792);
    __nv_bfloat16* Vs = (__nv_bfloat16*)(smem + 101376);
    float*         Bs = (float*)        (smem + 168960);
    float*         Sb = (float*)        (smem + 203776);
    __nv_bfloat16* Ps = (__nv_bfloat16*)(smem + 222208);
    int*           rg = (int*)          (smem + 231424);
    float*         linv = (float*)      (smem + 231680);
    float*         Os = (float*)Ks;                      // epilogue alias [64][260]

    int h  = blockIdx.x;
    int t  = threadIdx.x;
    int w  = t >> 5;
    int wr = w & 3, wc = w >> 2;

    const __nv_bfloat16* qh = g_qkv + (size_t)h*NTOK*DIM;
    const __nv_bfloat16* kh = g_qkv + (size_t)(NHEAD   + h)*NTOK*DIM;
    const __nv_bfloat16* vh = g_qkv + (size_t)(2*NHEAD + h)*NTOK*DIM;

    int mend = (Nv + 63) & ~63;
    int T = mend >> 6;

    auto prefetch = [&](int m, int st) {
        int m0 = m << 6;
        __nv_bfloat16* Kd = Ks + st*64*QS;
        __nv_bfloat16* Vd = Vs + st*64*QS;
        float*         Bd = Bs + st*64*68;
        #pragma unroll
        for (int k = 0; k < 8; k++) {
            int id = t + k*256;
            int r = id >> 5, c = (id & 31) << 3;
            cp16(Kd + r*QS + c, kh + (size_t)(m0+r)*DIM + c);
            cp16(Vd + r*QS + c, vh + (size_t)(m0+r)*DIM + c);
        }
        #pragma unroll
        for (int k = 0; k < 4; k++) {
            int id = t + k*256;
            int r = id >> 4, c = (id & 15) << 2;
            cp16(Bd + r*68 + c, g_bias + (size_t)(n0+r)*BSTRIDE + m0 + c);
        }
        cp_commit();
    };

    // Q + first tile prefetch (one group)
    #pragma unroll
    for (int k = 0; k < 8; k++) {
        int id = t + k*256;
        int r = id >> 5, c = (id & 31) << 3;
        cp16(Qs + r*QS + c, qh + (size_t)(n0+r)*DIM + c);
    }
    if (t < 64) rg[t] = g_idx[n0 + t];
    prefetch(0, 0);

    wmma::fragment<wmma::accumulator,16,16,16,float> o[8];
    #pragma unroll
    for (int j = 0; j < 8; j++) wmma::fill_fragment(o[j], 0.0f);

    float lsum = 0.f;
    int er = t >> 2;            // exp row (4 threads/row)
    int ec = (t & 3) << 4;      // 16 cols per thread
    bool rok = (n0 + er) < Nv;

    #pragma unroll 1
    for (int m = 0; m < T; m++) {
        cp_wait0();
        __syncthreads();                        // stage m ready; all done with m-1
        if (m + 1 < T) prefetch(m + 1, (m + 1) & 1);
        int st = m & 1;
        int m0 = m << 6;
        __nv_bfloat16* Kd = Ks + st*64*QS;
        __nv_bfloat16* Vd = Vs + st*64*QS;
        float*         Bd = Bs + st*64*68;

        // S = (q/16) K^T + bias (bias preloaded as accumulator)
        wmma::fragment<wmma::accumulator,16,16,16,float> sacc[2];
        #pragma unroll
        for (int j = 0; j < 2; j++)
            wmma::load_matrix_sync(sacc[j], Bd + (wr*16)*68 + wc*32 + j*16, 68, wmma::mem_row_major);
        #pragma unroll
        for (int kk = 0; kk < 16; kk++) {
            wmma::fragment<wmma::matrix_a,16,16,16,__nv_bfloat16,wmma::row_major> af;
            wmma::load_matrix_sync(af, Qs + (wr*16)*QS + kk*16, QS);
            #pragma unroll
            for (int j = 0; j < 2; j++) {
                wmma::fragment<wmma::matrix_b,16,16,16,__nv_bfloat16,wmma::col_major> bfr;
                wmma::load_matrix_sync(bfr, Kd + (wc*32 + j*16)*QS + kk*16, QS);
                wmma::mma_sync(sacc[j], af, bfr, sacc[j]);
            }
        }
        #pragma unroll
        for (int j = 0; j < 2; j++)
            wmma::store_matrix_sync(&Sb[(wr*16)*72 + wc*32 + j*16], sacc[j], 72, wmma::mem_row_major);
        __syncthreads();

        // masked exp (no max subtraction: logits bounded, fp32 safe)
        {
            float lp = 0.f;
            #pragma unroll
            for (int j = 0; j < 16; j++) {
                int c = ec + j;
                float s = Sb[er*72 + c];
                float p = (rok && (m0 + c) < Nv) ? __expf(s) : 0.f;
                lp += p;
                Ps[er*72 + c] = __float2bfloat16(p);
            }
            lsum += lp;
        }
        __syncthreads();

        // O += P @ V
        #pragma unroll
        for (int kk = 0; kk < 4; kk++) {
            wmma::fragment<wmma::matrix_a,16,16,16,__nv_bfloat16,wmma::row_major> af;
            wmma::load_matrix_sync(af, Ps + (wr*16)*72 + kk*16, 72);
            #pragma unroll
            for (int j = 0; j < 8; j++) {
                wmma::fragment<wmma::matrix_b,16,16,16,__nv_bfloat16,wmma::row_major> bfr;
                wmma::load_matrix_sync(bfr, Vd + (kk*16)*QS + wc*128 + j*16, QS);
                wmma::mma_sync(o[j], af, bfr, o[j]);
            }
        }
        // next iteration's top sync protects stage reuse
    }

    // row-sum reduce (4 consecutive lanes per row)
    lsum += __shfl_xor_sync(0xffffffffu, lsum, 1);
    lsum += __shfl_xor_sync(0xffffffffu, lsum, 2);
    if ((t & 3) == 0) linv[er] = (lsum > 0.f) ? (1.0f / lsum) : 0.0f;
    __syncthreads();

    #pragma unroll
    for (int j = 0; j < 8; j++)
        wmma::store_matrix_sync(&Os[(wr*16)*260 + wc*128 + j*16], o[j], 260, wmma::mem_row_major);
    __syncthreads();

    for (int i = t; i < 64*256; i += 256) {
        int r = i >> 8, c = i & 255;
        if (n0 + r < Nv) {
            float vv = Os[r*260 + c] * linv[r];
            g_cat[(size_t)rg[r]*(NHEAD*DIM) + h*DIM + c] = __float2bfloat16(vv);
        }
    }
}

// ---------------- launch ----------------
extern "C" void kernel_launch(void* const* d_in, const int* in_sizes, int n_in,
                              void* d_out, int out_size)
{
    (void)in_sizes; (void)n_in; (void)out_size;
    const float* x        = (const float*)d_in[0];
    const int*   mask_idx = (const int*)  d_in[1];
    const float* spatial  = (const float*)d_in[2];
    const float* edge     = (const float*)d_in[3];
    const float* ln1_g    = (const float*)d_in[4];
    const float* ln1_b    = (const float*)d_in[5];
    const float* Wq       = (const float*)d_in[6];
    const float* bq       = (const float*)d_in[7];
    const float* Wk       = (const float*)d_in[8];
    const float* bk       = (const float*)d_in[9];
    const float* Wv       = (const float*)d_in[10];
    const float* bv       = (const float*)d_in[11];
    const float* Wo       = (const float*)d_in[12];
    const float* bo       = (const float*)d_in[13];
    const float* ln2_g    = (const float*)d_in[14];
    const float* ln2_b    = (const float*)d_in[15];
    const float* Wff      = (const float*)d_in[16];
    const float* bff      = (const float*)d_in[17];
    float* out = (float*)d_out;

    cudaFuncSetAttribute((const void*)gemm_kernel<0,1,0>,
                         cudaFuncAttributeMaxDynamicSharedMemorySize, GEMM_SMEM);
    cudaFuncSetAttribute((const void*)gemm_kernel<1,0,1>,
                         cudaFuncAttributeMaxDynamicSharedMemorySize, GEMM_SMEM);
    cudaFuncSetAttribute((const void*)gemm_kernel<1,0,0>,
                         cudaFuncAttributeMaxDynamicSharedMemorySize, GEMM_SMEM);
    cudaFuncSetAttribute((const void*)attn_kernel,
                         cudaFuncAttributeMaxDynamicSharedMemorySize, ATT_SMEM);

    __nv_bfloat16 *xln, *qkv, *cat, *xln2, *wqkv, *wo, *wff;
    float *xout;
    cudaGetSymbolAddress((void**)&xln,  g_xln);
    cudaGetSymbolAddress((void**)&wqkv, g_wqkv);
    cudaGetSymbolAddress((void**)&wo,   g_wo);
    cudaGetSymbolAddress((void**)&wff,  g_wff);
    cudaGetSymbolAddress((void**)&qkv,  g_qkv);
    cudaGetSymbolAddress((void**)&cat,  g_cat);
    cudaGetSymbolAddress((void**)&xout, g_xout);
    cudaGetSymbolAddress((void**)&xln2, g_xln2);

    // (1) mask compaction
    compact_kernel<<<1, 1024>>>(mask_idx);

    // (2) fused weight conversions
    cvt_all_kernel<<<(4*HDD + DIM*DIM)/256, 256>>>(Wq, Wk, Wv, Wo, Wff);

    // (3) LN1 -> bf16, compacted rows
    ln_kernel<1><<<NTOK, 256>>>(x, ln1_g, ln1_b, xln);

    // (4) fused QKV projection on compacted rows
    gemm_kernel<0,1,0><<<dim3(32,48), 256, GEMM_SMEM>>>(xln, wqkv, DIM,
                                                        bq, bk, bv, nullptr, nullptr, qkv);

    // (5) compact bias precompute
    bias_pre_kernel<<<dim3(16, NTOK), 256>>>(spatial, edge);

    // (6) attention (profiled launch under ncu -s 5 -c 1)
    attn_kernel<<<dim3(NHEAD, NTOK/64), 256, ATT_SMEM>>>();

    // (7) output projection + residual (masked cat rows zero-filled at load)
    gemm_kernel<1,0,1><<<dim3(32,2), 256, GEMM_SMEM>>>(cat, wo, NHEAD*DIM,
                                                       bo, nullptr, nullptr, x, xout, nullptr);

    // (8) LN2 -> bf16 (full domain)
    ln_kernel<0><<<NTOK, 256>>>(xout, ln2_g, ln2_b, xln2);

    // (9) FF + residual
    gemm_kernel<1,0,0><<<dim3(32,2), 256, GEMM_SMEM>>>(xln2, wff, DIM,
                                                       bff, nullptr, nullptr, xout, out, nullptr);
}

// round 8
// speedup vs baseline: 1.2199x; 1.2199x over previous
#include <cuda_runtime.h>
#include <cuda_bf16.h>
#include <mma.h>
#include <cstdint>
using namespace nvcuda;

#define NTOK 4096
#define DIM 256
#define NHEAD 8
#define HDD (NHEAD*DIM*DIM)
#define BSTRIDE 4128
#define LOG2E 1.44269504088896f

__device__ __nv_bfloat16 g_xln [NTOK*DIM];
__device__ __nv_bfloat16 g_wqkv[3*HDD];
__device__ __nv_bfloat16 g_wo  [DIM*NHEAD*DIM];
__device__ __nv_bfloat16 g_wff [DIM*DIM];
__device__ __nv_bfloat16 g_qkv [3ULL*NHEAD*NTOK*DIM];
__device__ __nv_bfloat16 g_cat [(size_t)NTOK*NHEAD*DIM];
__device__ float         g_xout[NTOK*DIM];
__device__ __nv_bfloat16 g_xln2[NTOK*DIM];
__device__ float         g_bias[(size_t)NTOK*BSTRIDE];   // compact (sp+ed)*log2e
__device__ int g_nvalid, g_idx[NTOK], g_cidx[NTOK];

// ---- cp.async ----
__device__ __forceinline__ void cp16(void* d, const void* s) {
    uint32_t a = (uint32_t)__cvta_generic_to_shared(d);
    asm volatile("cp.async.cg.shared.global [%0], [%1], 16;\n" :: "r"(a), "l"(s));
}
__device__ __forceinline__ void cp16a(uint32_t a, const void* s) {
    asm volatile("cp.async.cg.shared.global [%0], [%1], 16;\n" :: "r"(a), "l"(s));
}
__device__ __forceinline__ void cp16p(void* d, const void* s, bool p) {
    uint32_t a = (uint32_t)__cvta_generic_to_shared(d);
    int sz = p ? 16 : 0;
    asm volatile("cp.async.cg.shared.global [%0], [%1], 16, %2;\n" :: "r"(a), "l"(s), "r"(sz));
}
__device__ __forceinline__ void cp_commit() { asm volatile("cp.async.commit_group;\n"); }
__device__ __forceinline__ void cp_wait0()  { asm volatile("cp.async.wait_group 0;\n"); }

// ---- mma.sync primitives ----
__device__ __forceinline__ void ldm4(uint32_t* r, uint32_t a) {
    asm volatile("ldmatrix.sync.aligned.m8n8.x4.shared.b16 {%0,%1,%2,%3}, [%4];"
        : "=r"(r[0]),"=r"(r[1]),"=r"(r[2]),"=r"(r[3]) : "r"(a));
}
__device__ __forceinline__ void ldm4t(uint32_t* r, uint32_t a) {
    asm volatile("ldmatrix.sync.aligned.m8n8.x4.trans.shared.b16 {%0,%1,%2,%3}, [%4];"
        : "=r"(r[0]),"=r"(r[1]),"=r"(r[2]),"=r"(r[3]) : "r"(a));
}
__device__ __forceinline__ void mma16816(float* c, const uint32_t* a, const uint32_t* b) {
    asm volatile("mma.sync.aligned.m16n8k16.row.col.f32.bf16.bf16.f32 "
        "{%0,%1,%2,%3}, {%4,%5,%6,%7}, {%8,%9}, {%0,%1,%2,%3};"
        : "+f"(c[0]),"+f"(c[1]),"+f"(c[2]),"+f"(c[3])
        : "r"(a[0]),"r"(a[1]),"r"(a[2]),"r"(a[3]), "r"(b[0]),"r"(b[1]));
}
__device__ __forceinline__ float ex2f(float x) { float y; asm("ex2.approx.ftz.f32 %0, %1;" : "=f"(y) : "f"(x)); return y; }
__device__ __forceinline__ uint32_t packbf(float hi, float lo) {
    uint32_t r; asm("cvt.rn.bf16x2.f32 %0, %1, %2;" : "=r"(r) : "f"(hi), "f"(lo)); return r;
}

// ---- mask compaction ----
__global__ void compact_kernel(const int* __restrict__ mask)
{
    __shared__ int ws[32];
    int t = threadIdx.x, base = t*4, m[4], s = 0;
    #pragma unroll
    for (int i=0;i<4;i++){ m[i] = (mask[base+i] != 0); s += m[i]; }
    int lane = t&31, w = t>>5, pre = s;
    #pragma unroll
    for (int o=1;o<32;o<<=1){ int v = __shfl_up_sync(~0u, pre, o); if (lane >= o) pre += v; }
    if (lane == 31) ws[w] = pre;
    __syncthreads();
    if (t < 32) {
        int v = ws[t];
        #pragma unroll
        for (int o=1;o<32;o<<=1){ int u = __shfl_up_sync(~0u, v, o); if (t >= o) v += u; }
        ws[t] = v;
    }
    __syncthreads();
    int off = pre - s + ((w > 0) ? ws[w-1] : 0);
    #pragma unroll
    for (int i=0;i<4;i++){
        if (m[i]) { g_idx[off] = base+i; g_cidx[base+i] = off; off++; }
        else      g_cidx[base+i] = -1;
    }
    if (t == 0) g_nvalid = ws[31];
}

__global__ void cvt_all_kernel(const float* __restrict__ Wq, const float* __restrict__ Wk,
                               const float* __restrict__ Wv, const float* __restrict__ Wo,
                               const float* __restrict__ Wff)
{
    int i = blockIdx.x*256 + threadIdx.x;
    if      (i <   HDD) g_wqkv[i] = __float2bfloat16(Wq[i]);
    else if (i < 2*HDD) g_wqkv[i] = __float2bfloat16(Wk[i-HDD]);
    else if (i < 3*HDD) g_wqkv[i] = __float2bfloat16(Wv[i-2*HDD]);
    else if (i < 4*HDD) g_wo [i-3*HDD] = __float2bfloat16(Wo [i-3*HDD]);
    else                g_wff[i-4*HDD] = __float2bfloat16(Wff[i-4*HDD]);
}

template<int COMPACT>
__global__ void ln_kernel(const float* __restrict__ x, const float* __restrict__ g,
                          const float* __restrict__ b, __nv_bfloat16* __restrict__ out)
{
    int row = blockIdx.x, orow = row;
    if (COMPACT) { orow = g_cidx[row]; if (orow < 0) return; }
    int t = threadIdx.x;
    float v = x[row*DIM + t], sum = v, sq = v*v;
    #pragma unroll
    for (int o=16;o>0;o>>=1){ sum += __shfl_xor_sync(~0u,sum,o); sq += __shfl_xor_sync(~0u,sq,o); }
    __shared__ float s1[8], s2[8];
    if ((t&31)==0){ s1[t>>5]=sum; s2[t>>5]=sq; }
    __syncthreads();
    __shared__ float smu, srstd;
    if (t == 0) {
        float S=0, Q=0;
        #pragma unroll
        for (int i=0;i<8;i++){ S+=s1[i]; Q+=s2[i]; }
        float m = S*(1.f/DIM);
        smu = m; srstd = rsqrtf(Q*(1.f/DIM) - m*m + 1e-5f);
    }
    __syncthreads();
    out[orow*DIM + t] = __float2bfloat16((v - smu)*srstd*g[t] + b[t]);
}

// ---- compact bias precompute: contiguous row reads, column scatter ----
__global__ void bias_pre_kernel(const float* __restrict__ sp, const float* __restrict__ ed)
{
    int i = blockIdx.y;
    if (i >= g_nvalid) return;
    int j = blockIdx.x*256 + threadIdx.x;
    int gi = g_idx[i];
    float v = (sp[(size_t)gi*NTOK + j] + ed[(size_t)gi*NTOK + j]) * LOG2E;
    int cj = g_cidx[j];
    if (cj >= 0) g_bias[(size_t)i*BSTRIDE + cj] = v;
}

// ---- WMMA GEMM (round-3; Q scale folds log2e) ----
#define GEMM_SMEM (4*128*72*2 > 128*132*4 ? 4*128*72*2 : 128*132*4)
template<int EPI, int COMPACT, int ZMASK>
__global__ void gemm_kernel(const __nv_bfloat16* __restrict__ A, const __nv_bfloat16* __restrict__ B,
                            int K, const float* __restrict__ b0, const float* __restrict__ b1,
                            const float* __restrict__ b2, const float* __restrict__ res,
                            float* __restrict__ outf, __nv_bfloat16* __restrict__ outb)
{
    int bm = blockIdx.x * 128;
    if (COMPACT && bm >= g_nvalid) return;
    extern __shared__ char smem[];
    __nv_bfloat16* As = (__nv_bfloat16*)smem;
    __nv_bfloat16* Bs = As + 2*128*72;
    float* Cs = (float*)smem;
    int bn = blockIdx.y * 128, t = threadIdx.x, w = t>>5;
    int wr = w & 3, wc = w >> 2;
    bool pm[4];
    #pragma unroll
    for (int k=0;k<4;k++){ int r = (t + k*256) >> 3; pm[k] = !ZMASK || (g_cidx[bm+r] >= 0); }
    wmma::fragment<wmma::accumulator,16,16,16,float> acc[2][4];
    #pragma unroll
    for (int i=0;i<2;i++)
        #pragma unroll
        for (int j=0;j<4;j++) wmma::fill_fragment(acc[i][j], 0.f);
    int nP = K >> 6;
    auto pref = [&](int p, int st){
        const __nv_bfloat16* Ap = A + (size_t)bm*K + p*64;
        const __nv_bfloat16* Bp = B + (size_t)bn*K + p*64;
        __nv_bfloat16* Ad = As + st*128*72;
        __nv_bfloat16* Bd = Bs + st*128*72;
        #pragma unroll
        for (int k=0;k<4;k++){
            int id = t + k*256, r = id>>3, c = (id&7)<<3;
            cp16p(Ad + r*72 + c, Ap + (size_t)r*K + c, pm[k]);
            cp16 (Bd + r*72 + c, Bp + (size_t)r*K + c);
        }
        cp_commit();
    };
    pref(0, 0);
    for (int p=0;p<nP;p++){
        cp_wait0(); __syncthreads();
        if (p+1 < nP) pref(p+1, (p+1)&1);
        int st = p & 1;
        __nv_bfloat16* Ad = As + st*128*72;
        __nv_bfloat16* Bd = Bs + st*128*72;
        #pragma unroll
        for (int kk=0;kk<4;kk++){
            wmma::fragment<wmma::matrix_a,16,16,16,__nv_bfloat16,wmma::row_major> af[2];
            #pragma unroll
            for (int i=0;i<2;i++) wmma::load_matrix_sync(af[i], Ad + (wr*32+i*16)*72 + kk*16, 72);
            #pragma unroll
            for (int j=0;j<4;j++){
                wmma::fragment<wmma::matrix_b,16,16,16,__nv_bfloat16,wmma::col_major> bf;
                wmma::load_matrix_sync(bf, Bd + (wc*64+j*16)*72 + kk*16, 72);
                #pragma unroll
                for (int i=0;i<2;i++) wmma::mma_sync(acc[i][j], af[i], bf, acc[i][j]);
            }
        }
        __syncthreads();
    }
    #pragma unroll
    for (int i=0;i<2;i++)
        #pragma unroll
        for (int j=0;j<4;j++)
            wmma::store_matrix_sync(&Cs[(wr*32+i*16)*132 + wc*64 + j*16], acc[i][j], 132, wmma::mem_row_major);
    __syncthreads();
    for (int idx=t; idx<128*128; idx+=256){
        int r = idx>>7, c = idx&127, n = bm+r, cc = bn+c;
        float v = Cs[r*132 + c];
        if (EPI == 0) {
            int which = cc >> 11;
            const float* bp = (which==0) ? b0 : (which==1) ? b1 : b2;
            v += bp[cc & 2047];
            if (which == 0) v *= 0.0625f*LOG2E;          // fold log2e into q
            int h = (cc>>8)&7, e = cc&255;
            outb[((size_t)which*NHEAD + h)*NTOK*DIM + (size_t)n*DIM + e] = __float2bfloat16(v);
        } else {
            v += b0[cc] + res[(size_t)n*DIM + cc];
            outf[(size_t)n*DIM + cc] = v;
        }
    }
}

// ---- FA2-style mma.sync attention ----
// 256 thr, 8 warps = 4 row-groups x 2 D-split. BM=64 q rows, BN=64 kv per tile.
// smem: Q 64x528B @0 | K 2x(64x528) @33792 | V 2x(64x528) @101376 | bias 2x(64x272B) @168960
#define AT_KB 33792
#define AT_VB 101376
#define AT_BB 168960
#define ATT_SMEM 203776

__global__ void __launch_bounds__(256,1) attn_kernel()
{
    int Nv = g_nvalid;
    int h = blockIdx.x, n0 = blockIdx.y*64;
    if (n0 >= Nv) return;
    extern __shared__ char smem[];
    uint32_t sb = (uint32_t)__cvta_generic_to_shared(smem);
    int t = threadIdx.x, lane = t&31, w = t>>5;
    int g = w>>1, dh = w&1;

    const __nv_bfloat16* qh = g_qkv + (size_t)h*NTOK*DIM;
    const __nv_bfloat16* kh = g_qkv + (size_t)(NHEAD+h)*NTOK*DIM;
    const __nv_bfloat16* vh = g_qkv + (size_t)(2*NHEAD+h)*NTOK*DIM;

    auto pref = [&](int m){
        int st = m&1, m0 = m<<6;
        uint32_t kb = sb + AT_KB + st*33792u;
        uint32_t vb = sb + AT_VB + st*33792u;
        uint32_t bb = sb + AT_BB + st*17408u;
        #pragma unroll
        for (int i=0;i<8;i++){
            int id = t + i*256, r = id>>5, c = id&31;
            cp16a(kb + r*528 + c*16, kh + (size_t)(m0+r)*DIM + c*8);
            cp16a(vb + r*528 + c*16, vh + (size_t)(m0+r)*DIM + c*8);
        }
        #pragma unroll
        for (int i=0;i<4;i++){
            int id = t + i*256, r = id>>4, c = id&15;   // FIXED: 64 rows x 16 chunks
            cp16a(bb + r*272 + c*16, g_bias + (size_t)(n0+r)*BSTRIDE + m0 + c*4);
        }
        cp_commit();
    };

    // stage Q + first K/V/bias in one group
    #pragma unroll
    for (int i=0;i<8;i++){
        int id = t + i*256, r = id>>5, c = id&31;
        cp16a(sb + r*528 + c*16, qh + (size_t)(n0+r)*DIM + c*8);
    }
    pref(0);

    // per-lane ldmatrix address components
    int sub = lane>>3;
    uint32_t qaddr = sb + (uint32_t)(g*16 + (lane&15))*528 + (uint32_t)((lane>>4)<<3)*2;
    uint32_t krow = (uint32_t)(((sub>>1)<<3) + (lane&7));
    uint32_t kcol = (uint32_t)((sub&1)<<3);
    uint32_t vrow = (uint32_t)(((sub&1)<<3) + (lane&7));
    uint32_t vcol = (uint32_t)(dh*128 + ((sub>>1)<<3));
    int r0 = g*16 + (lane>>2);
    int c0 = (lane&3)*2;

    float o[16][4];
    #pragma unroll
    for (int u=0;u<16;u++){ o[u][0]=0;o[u][1]=0;o[u][2]=0;o[u][3]=0; }
    float ls0 = 0.f, ls1 = 0.f;
    int T = (Nv + 63) >> 6;

    for (int m=0; m<T; m++){
        cp_wait0();
        __syncthreads();
        if (m+1 < T) pref(m+1);
        int st = m&1, m0 = m<<6;
        uint32_t kb = sb + AT_KB + st*33792u;
        uint32_t vb = sb + AT_VB + st*33792u;
        const char* bb = smem + AT_BB + st*17408;

        // S accumulators init = bias (already *log2e)
        float c[8][4];
        #pragma unroll
        for (int j=0;j<8;j++){
            float2 lo = *(const float2*)(bb + r0*272     + (j*8+c0)*4);
            float2 hi = *(const float2*)(bb + (r0+8)*272 + (j*8+c0)*4);
            c[j][0]=lo.x; c[j][1]=lo.y; c[j][2]=hi.x; c[j][3]=hi.y;
        }
        // S += Q K^T (Q pre-scaled by log2e/16)
        #pragma unroll
        for (int kt=0; kt<16; kt++){
            uint32_t qa[4];
            ldm4(qa, qaddr + kt*32);
            uint32_t kf[16];
            #pragma unroll
            for (int jp=0;jp<4;jp++)
                ldm4(kf + jp*4, kb + (jp*16 + krow)*528 + (kt*16 + kcol)*2);
            #pragma unroll
            for (int j=0;j<8;j++)
                mma16816(c[j], qa, kf + (j>>1)*4 + (j&1)*2);
        }
        // exp + pack P into A-fragments (registers only)
        uint32_t pa[4][4];
        #pragma unroll
        for (int j=0;j<8;j++){
            bool ok0 = (m0 + j*8 + c0    ) < Nv;
            bool ok1 = (m0 + j*8 + c0 + 1) < Nv;
            float p0 = ok0 ? ex2f(c[j][0]) : 0.f;
            float p1 = ok1 ? ex2f(c[j][1]) : 0.f;
            float p2 = ok0 ? ex2f(c[j][2]) : 0.f;
            float p3 = ok1 ? ex2f(c[j][3]) : 0.f;
            ls0 += p0 + p1; ls1 += p2 + p3;
            int tt = j>>1;
            if ((j&1)==0){ pa[tt][0] = packbf(p1,p0); pa[tt][1] = packbf(p3,p2); }
            else         { pa[tt][2] = packbf(p1,p0); pa[tt][3] = packbf(p3,p2); }
        }
        // O += P V (this warp's 128-col D half)
        #pragma unroll
        for (int tt=0;tt<4;tt++){
            #pragma unroll
            for (int up=0;up<8;up++){
                uint32_t vf[4];
                ldm4t(vf, vb + (tt*16 + vrow)*528 + (vcol + up*16)*2);
                mma16816(o[2*up],   pa[tt], vf);
                mma16816(o[2*up+1], pa[tt], vf+2);
            }
        }
    }

    // row sums over the 4 lanes sharing each row
    ls0 += __shfl_xor_sync(~0u, ls0, 1); ls0 += __shfl_xor_sync(~0u, ls0, 2);
    ls1 += __shfl_xor_sync(~0u, ls1, 1); ls1 += __shfl_xor_sync(~0u, ls1, 2);
    float inv0 = ls0 > 0.f ? 1.f/ls0 : 0.f;
    float inv1 = ls1 > 0.f ? 1.f/ls1 : 0.f;

    bool rok0 = (n0 + r0)     < Nv;
    bool rok1 = (n0 + r0 + 8) < Nv;
    int gi0 = rok0 ? g_idx[n0 + r0]     : 0;
    int gi1 = rok1 ? g_idx[n0 + r0 + 8] : 0;
    __nv_bfloat16* d0 = g_cat + (size_t)gi0*(NHEAD*DIM) + h*DIM + dh*128 + c0;
    __nv_bfloat16* d1 = g_cat + (size_t)gi1*(NHEAD*DIM) + h*DIM + dh*128 + c0;
    #pragma unroll
    for (int u=0;u<16;u++){
        if (rok0) *(uint32_t*)(d0 + u*8) = packbf(o[u][1]*inv0, o[u][0]*inv0);
        if (rok1) *(uint32_t*)(d1 + u*8) = packbf(o[u][3]*inv1, o[u][2]*inv1);
    }
}

extern "C" void kernel_launch(void* const* d_in, const int* in_sizes, int n_in,
                              void* d_out, int out_size)
{
    (void)in_sizes; (void)n_in; (void)out_size;
    const float* x       = (const float*)d_in[0];
    const int*   mask    = (const int*)  d_in[1];
    const float* spatial = (const float*)d_in[2];
    const float* edge    = (const float*)d_in[3];
    const float* ln1_g   = (const float*)d_in[4];
    const float* ln1_b   = (const float*)d_in[5];
    const float* Wq = (const float*)d_in[6],  *bq = (const float*)d_in[7];
    const float* Wk = (const float*)d_in[8],  *bk = (const float*)d_in[9];
    const float* Wv = (const float*)d_in[10], *bv = (const float*)d_in[11];
    const float* Wo = (const float*)d_in[12], *bo = (const float*)d_in[13];
    const float* ln2_g = (const float*)d_in[14], *ln2_b = (const float*)d_in[15];
    const float* Wff = (const float*)d_in[16], *bff = (const float*)d_in[17];
    float* out = (float*)d_out;

    cudaFuncSetAttribute((const void*)gemm_kernel<0,1,0>, cudaFuncAttributeMaxDynamicSharedMemorySize, GEMM_SMEM);
    cudaFuncSetAttribute((const void*)gemm_kernel<1,0,1>, cudaFuncAttributeMaxDynamicSharedMemorySize, GEMM_SMEM);
    cudaFuncSetAttribute((const void*)gemm_kernel<1,0,0>, cudaFuncAttributeMaxDynamicSharedMemorySize, GEMM_SMEM);
    cudaFuncSetAttribute((const void*)attn_kernel, cudaFuncAttributeMaxDynamicSharedMemorySize, ATT_SMEM);

    __nv_bfloat16 *xln, *qkv, *cat, *xln2, *wqkv, *wo, *wff;
    float *xout;
    cudaGetSymbolAddress((void**)&xln,  g_xln);
    cudaGetSymbolAddress((void**)&wqkv, g_wqkv);
    cudaGetSymbolAddress((void**)&wo,   g_wo);
    cudaGetSymbolAddress((void**)&wff,  g_wff);
    cudaGetSymbolAddress((void**)&qkv,  g_qkv);
    cudaGetSymbolAddress((void**)&cat,  g_cat);
    cudaGetSymbolAddress((void**)&xout, g_xout);
    cudaGetSymbolAddress((void**)&xln2, g_xln2);

    compact_kernel<<<1, 1024>>>(mask);                                            // 1
    cvt_all_kernel<<<(4*HDD + DIM*DIM)/256, 256>>>(Wq, Wk, Wv, Wo, Wff);          // 2
    ln_kernel<1><<<NTOK, 256>>>(x, ln1_g, ln1_b, xln);                            // 3
    gemm_kernel<0,1,0><<<dim3(32,48), 256, GEMM_SMEM>>>(xln, wqkv, DIM,
                                                        bq, bk, bv, nullptr, nullptr, qkv); // 4
    bias_pre_kernel<<<dim3(16, NTOK), 256>>>(spatial, edge);                      // 5
    attn_kernel<<<dim3(NHEAD, NTOK/64), 256, ATT_SMEM>>>();                       // 6 (profiled)
    gemm_kernel<1,0,1><<<dim3(32,2), 256, GEMM_SMEM>>>(cat, wo, NHEAD*DIM,
                                                       bo, nullptr, nullptr, x, xout, nullptr);
    ln_kernel<0><<<NTOK, 256>>>(xout, ln2_g, ln2_b, xln2);
    gemm_kernel<1,0,0><<<dim3(32,2), 256, GEMM_SMEM>>>(xln2, wff, DIM,
                                                       bff, nullptr, nullptr, xout, out, nullptr);
}

// round 9
// speedup vs baseline: 1.3642x; 1.1183x over previous
#include <cuda_runtime.h>
#include <cuda_bf16.h>
#include <mma.h>
#include <cstdint>
using namespace nvcuda;

#define NTOK 4096
#define DIM 256
#define NHEAD 8
#define HDD (NHEAD*DIM*DIM)
#define BSTRIDE 4128
#define LOG2E 1.44269504088896f

__device__ __nv_bfloat16 g_xln [NTOK*DIM];
__device__ __nv_bfloat16 g_wqkv[3*HDD];
__device__ __nv_bfloat16 g_wo  [DIM*NHEAD*DIM];
__device__ __nv_bfloat16 g_wff [DIM*DIM];
__device__ __nv_bfloat16 g_qkv [3ULL*NHEAD*NTOK*DIM];
__device__ __nv_bfloat16 g_cat [(size_t)NTOK*NHEAD*DIM];
__device__ float         g_xout[NTOK*DIM];
__device__ __nv_bfloat16 g_xln2[NTOK*DIM];
__device__ float         g_bias[(size_t)NTOK*BSTRIDE];   // compact (sp+ed)*log2e
__device__ int g_nvalid, g_idx[NTOK], g_cidx[NTOK];

// ---- cp.async ----
__device__ __forceinline__ void cp16(void* d, const void* s) {
    uint32_t a = (uint32_t)__cvta_generic_to_shared(d);
    asm volatile("cp.async.cg.shared.global [%0], [%1], 16;\n" :: "r"(a), "l"(s));
}
__device__ __forceinline__ void cp16a(uint32_t a, const void* s) {
    asm volatile("cp.async.cg.shared.global [%0], [%1], 16;\n" :: "r"(a), "l"(s));
}
__device__ __forceinline__ void cp16p(void* d, const void* s, bool p) {
    uint32_t a = (uint32_t)__cvta_generic_to_shared(d);
    int sz = p ? 16 : 0;
    asm volatile("cp.async.cg.shared.global [%0], [%1], 16, %2;\n" :: "r"(a), "l"(s), "r"(sz));
}
__device__ __forceinline__ void cp_commit() { asm volatile("cp.async.commit_group;\n"); }
__device__ __forceinline__ void cp_wait0()  { asm volatile("cp.async.wait_group 0;\n"); }

// ---- mma.sync primitives ----
__device__ __forceinline__ void ldm4(uint32_t* r, uint32_t a) {
    asm volatile("ldmatrix.sync.aligned.m8n8.x4.shared.b16 {%0,%1,%2,%3}, [%4];"
        : "=r"(r[0]),"=r"(r[1]),"=r"(r[2]),"=r"(r[3]) : "r"(a));
}
__device__ __forceinline__ void ldm4t(uint32_t* r, uint32_t a) {
    asm volatile("ldmatrix.sync.aligned.m8n8.x4.trans.shared.b16 {%0,%1,%2,%3}, [%4];"
        : "=r"(r[0]),"=r"(r[1]),"=r"(r[2]),"=r"(r[3]) : "r"(a));
}
__device__ __forceinline__ void mma16816(float* c, const uint32_t* a, const uint32_t* b) {
    asm volatile("mma.sync.aligned.m16n8k16.row.col.f32.bf16.bf16.f32 "
        "{%0,%1,%2,%3}, {%4,%5,%6,%7}, {%8,%9}, {%0,%1,%2,%3};"
        : "+f"(c[0]),"+f"(c[1]),"+f"(c[2]),"+f"(c[3])
        : "r"(a[0]),"r"(a[1]),"r"(a[2]),"r"(a[3]), "r"(b[0]),"r"(b[1]));
}
__device__ __forceinline__ float ex2f(float x) { float y; asm("ex2.approx.ftz.f32 %0, %1;" : "=f"(y) : "f"(x)); return y; }
__device__ __forceinline__ uint32_t packbf(float hi, float lo) {
    uint32_t r; asm("cvt.rn.bf16x2.f32 %0, %1, %2;" : "=r"(r) : "f"(hi), "f"(lo)); return r;
}
__device__ __forceinline__ void sts32(uint32_t a, uint32_t v) {
    asm volatile("st.shared.u32 [%0], %1;" :: "r"(a), "r"(v) : "memory");
}

// ---- mask compaction ----
__global__ void compact_kernel(const int* __restrict__ mask)
{
    __shared__ int ws[32];
    int t = threadIdx.x, base = t*4, m[4], s = 0;
    #pragma unroll
    for (int i=0;i<4;i++){ m[i] = (mask[base+i] != 0); s += m[i]; }
    int lane = t&31, w = t>>5, pre = s;
    #pragma unroll
    for (int o=1;o<32;o<<=1){ int v = __shfl_up_sync(~0u, pre, o); if (lane >= o) pre += v; }
    if (lane == 31) ws[w] = pre;
    __syncthreads();
    if (t < 32) {
        int v = ws[t];
        #pragma unroll
        for (int o=1;o<32;o<<=1){ int u = __shfl_up_sync(~0u, v, o); if (t >= o) v += u; }
        ws[t] = v;
    }
    __syncthreads();
    int off = pre - s + ((w > 0) ? ws[w-1] : 0);
    #pragma unroll
    for (int i=0;i<4;i++){
        if (m[i]) { g_idx[off] = base+i; g_cidx[base+i] = off; off++; }
        else      g_cidx[base+i] = -1;
    }
    if (t == 0) g_nvalid = ws[31];
}

__global__ void cvt_all_kernel(const float* __restrict__ Wq, const float* __restrict__ Wk,
                               const float* __restrict__ Wv, const float* __restrict__ Wo,
                               const float* __restrict__ Wff)
{
    int i = blockIdx.x*256 + threadIdx.x;
    if      (i <   HDD) g_wqkv[i] = __float2bfloat16(Wq[i]);
    else if (i < 2*HDD) g_wqkv[i] = __float2bfloat16(Wk[i-HDD]);
    else if (i < 3*HDD) g_wqkv[i] = __float2bfloat16(Wv[i-2*HDD]);
    else if (i < 4*HDD) g_wo [i-3*HDD] = __float2bfloat16(Wo [i-3*HDD]);
    else                g_wff[i-4*HDD] = __float2bfloat16(Wff[i-4*HDD]);
}

template<int COMPACT>
__global__ void ln_kernel(const float* __restrict__ x, const float* __restrict__ g,
                          const float* __restrict__ b, __nv_bfloat16* __restrict__ out)
{
    int row = blockIdx.x, orow = row;
    if (COMPACT) { orow = g_cidx[row]; if (orow < 0) return; }
    int t = threadIdx.x;
    float v = x[row*DIM + t], sum = v, sq = v*v;
    #pragma unroll
    for (int o=16;o>0;o>>=1){ sum += __shfl_xor_sync(~0u,sum,o); sq += __shfl_xor_sync(~0u,sq,o); }
    __shared__ float s1[8], s2[8];
    if ((t&31)==0){ s1[t>>5]=sum; s2[t>>5]=sq; }
    __syncthreads();
    __shared__ float smu, srstd;
    if (t == 0) {
        float S=0, Q=0;
        #pragma unroll
        for (int i=0;i<8;i++){ S+=s1[i]; Q+=s2[i]; }
        float m = S*(1.f/DIM);
        smu = m; srstd = rsqrtf(Q*(1.f/DIM) - m*m + 1e-5f);
    }
    __syncthreads();
    out[orow*DIM + t] = __float2bfloat16((v - smu)*srstd*g[t] + b[t]);
}

// ---- compact bias precompute: contiguous row reads, column scatter ----
__global__ void bias_pre_kernel(const float* __restrict__ sp, const float* __restrict__ ed)
{
    int i = blockIdx.y;
    if (i >= g_nvalid) return;
    int j = blockIdx.x*256 + threadIdx.x;
    int gi = g_idx[i];
    float v = (sp[(size_t)gi*NTOK + j] + ed[(size_t)gi*NTOK + j]) * LOG2E;
    int cj = g_cidx[j];
    if (cj >= 0) g_bias[(size_t)i*BSTRIDE + cj] = v;
}

// ---- WMMA GEMM (Q scale folds log2e) ----
#define GEMM_SMEM (4*128*72*2 > 128*132*4 ? 4*128*72*2 : 128*132*4)
template<int EPI, int COMPACT, int ZMASK>
__global__ void gemm_kernel(const __nv_bfloat16* __restrict__ A, const __nv_bfloat16* __restrict__ B,
                            int K, const float* __restrict__ b0, const float* __restrict__ b1,
                            const float* __restrict__ b2, const float* __restrict__ res,
                            float* __restrict__ outf, __nv_bfloat16* __restrict__ outb)
{
    int bm = blockIdx.x * 128;
    if (COMPACT && bm >= g_nvalid) return;
    extern __shared__ char smem[];
    __nv_bfloat16* As = (__nv_bfloat16*)smem;
    __nv_bfloat16* Bs = As + 2*128*72;
    float* Cs = (float*)smem;
    int bn = blockIdx.y * 128, t = threadIdx.x, w = t>>5;
    int wr = w & 3, wc = w >> 2;
    bool pm[4];
    #pragma unroll
    for (int k=0;k<4;k++){ int r = (t + k*256) >> 3; pm[k] = !ZMASK || (g_cidx[bm+r] >= 0); }
    wmma::fragment<wmma::accumulator,16,16,16,float> acc[2][4];
    #pragma unroll
    for (int i=0;i<2;i++)
        #pragma unroll
        for (int j=0;j<4;j++) wmma::fill_fragment(acc[i][j], 0.f);
    int nP = K >> 6;
    auto pref = [&](int p, int st){
        const __nv_bfloat16* Ap = A + (size_t)bm*K + p*64;
        const __nv_bfloat16* Bp = B + (size_t)bn*K + p*64;
        __nv_bfloat16* Ad = As + st*128*72;
        __nv_bfloat16* Bd = Bs + st*128*72;
        #pragma unroll
        for (int k=0;k<4;k++){
            int id = t + k*256, r = id>>3, c = (id&7)<<3;
            cp16p(Ad + r*72 + c, Ap + (size_t)r*K + c, pm[k]);
            cp16 (Bd + r*72 + c, Bp + (size_t)r*K + c);
        }
        cp_commit();
    };
    pref(0, 0);
    for (int p=0;p<nP;p++){
        cp_wait0(); __syncthreads();
        if (p+1 < nP) pref(p+1, (p+1)&1);
        int st = p & 1;
        __nv_bfloat16* Ad = As + st*128*72;
        __nv_bfloat16* Bd = Bs + st*128*72;
        #pragma unroll
        for (int kk=0;kk<4;kk++){
            wmma::fragment<wmma::matrix_a,16,16,16,__nv_bfloat16,wmma::row_major> af[2];
            #pragma unroll
            for (int i=0;i<2;i++) wmma::load_matrix_sync(af[i], Ad + (wr*32+i*16)*72 + kk*16, 72);
            #pragma unroll
            for (int j=0;j<4;j++){
                wmma::fragment<wmma::matrix_b,16,16,16,__nv_bfloat16,wmma::col_major> bf;
                wmma::load_matrix_sync(bf, Bd + (wc*64+j*16)*72 + kk*16, 72);
                #pragma unroll
                for (int i=0;i<2;i++) wmma::mma_sync(acc[i][j], af[i], bf, acc[i][j]);
            }
        }
        __syncthreads();
    }
    #pragma unroll
    for (int i=0;i<2;i++)
        #pragma unroll
        for (int j=0;j<4;j++)
            wmma::store_matrix_sync(&Cs[(wr*32+i*16)*132 + wc*64 + j*16], acc[i][j], 132, wmma::mem_row_major);
    __syncthreads();
    for (int idx=t; idx<128*128; idx+=256){
        int r = idx>>7, c = idx&127, n = bm+r, cc = bn+c;
        float v = Cs[r*132 + c];
        if (EPI == 0) {
            int which = cc >> 11;
            const float* bp = (which==0) ? b0 : (which==1) ? b1 : b2;
            v += bp[cc & 2047];
            if (which == 0) v *= 0.0625f*LOG2E;
            int h = (cc>>8)&7, e = cc&255;
            outb[((size_t)which*NHEAD + h)*NTOK*DIM + (size_t)n*DIM + e] = __float2bfloat16(v);
        } else {
            v += b0[cc] + res[(size_t)n*DIM + cc];
            outf[(size_t)n*DIM + cc] = v;
        }
    }
}

// ---- FA2 attention with QK dedup via smem P-exchange ----
// 256 thr, 8 warps. Warps 0-3: QK+exp+pack (rows w*16..+15) + PV (D cols 0-127).
// Warps 4-7: PV only (D cols 128-255), P via ldmatrix from smem.
// smem: Q 64x528B @0 | K 2x(64x528) @33792 | V 2x(64x528) @101376 |
//       bias 2x(64x272B) @168960 | P 2x(64x144B) @203776 | linv @222208
#define AT_KB 33792
#define AT_VB 101376
#define AT_BB 168960
#define AT_PB 203776
#define AT_LV 222208
#define ATT_SMEM 222464

__global__ void __launch_bounds__(256,1) attn_kernel()
{
    int Nv = g_nvalid;
    int h = blockIdx.x, n0 = blockIdx.y*64;
    if (n0 >= Nv) return;
    extern __shared__ char smem[];
    uint32_t sb = (uint32_t)__cvta_generic_to_shared(smem);
    float* linv_sm = (float*)(smem + AT_LV);
    int t = threadIdx.x, lane = t&31, w = t>>5;
    int g2 = w & 3, dh = w >> 2;        // PV role: rows g2*16.., D-half dh
    bool isqk = (w < 4);                // QK role: warps 0-3 (one per SMSP)

    const __nv_bfloat16* qh = g_qkv + (size_t)h*NTOK*DIM;
    const __nv_bfloat16* kh = g_qkv + (size_t)(NHEAD+h)*NTOK*DIM;
    const __nv_bfloat16* vh = g_qkv + (size_t)(2*NHEAD+h)*NTOK*DIM;

    auto pref = [&](int m){
        int st = m&1, m0 = m<<6;
        uint32_t kb = sb + AT_KB + st*33792u;
        uint32_t vb = sb + AT_VB + st*33792u;
        uint32_t bb = sb + AT_BB + st*17408u;
        #pragma unroll
        for (int i=0;i<8;i++){
            int id = t + i*256, r = id>>5, c = id&31;
            cp16a(kb + r*528 + c*16, kh + (size_t)(m0+r)*DIM + c*8);
            cp16a(vb + r*528 + c*16, vh + (size_t)(m0+r)*DIM + c*8);
        }
        #pragma unroll
        for (int i=0;i<4;i++){
            int id = t + i*256, r = id>>4, c = id&15;
            cp16a(bb + r*272 + c*16, g_bias + (size_t)(n0+r)*BSTRIDE + m0 + c*4);
        }
        cp_commit();
    };

    // stage Q + first K/V/bias
    #pragma unroll
    for (int i=0;i<8;i++){
        int id = t + i*256, r = id>>5, c = id&31;
        cp16a(sb + r*528 + c*16, qh + (size_t)(n0+r)*DIM + c*8);
    }
    pref(0);

    // per-lane address components
    int sub = lane>>3;
    uint32_t qaddr = sb + (uint32_t)(g2*16 + (lane&15))*528 + (uint32_t)((lane>>4)<<3)*2;
    uint32_t krow = (uint32_t)(((sub>>1)<<3) + (lane&7));
    uint32_t kcol = (uint32_t)((sub&1)<<3);
    uint32_t vrow = (uint32_t)(((sub&1)<<3) + (lane&7));
    uint32_t vcol = (uint32_t)(dh*128 + ((sub>>1)<<3));
    int r0 = g2*16 + (lane>>2);
    int c0 = (lane&3)*2;
    uint32_t pld = (uint32_t)((g2*16 + (lane&15))*144 + ((lane>>4)<<4));  // P ldmatrix
    uint32_t pst = (uint32_t)(r0*144 + c0*2);                              // P store

    float o[16][4];
    #pragma unroll
    for (int u=0;u<16;u++){ o[u][0]=0;o[u][1]=0;o[u][2]=0;o[u][3]=0; }
    float ls0 = 0.f, ls1 = 0.f;
    int T = (Nv + 63) >> 6;

    for (int m=0; m<T; m++){
        cp_wait0();
        __syncthreads();                 // K/V/bias[m] ready; P[m&1] free
        if (m+1 < T) pref(m+1);
        int st = m&1, m0 = m<<6;
        uint32_t kb = sb + AT_KB + st*33792u;
        uint32_t vb = sb + AT_VB + st*33792u;
        uint32_t pb = sb + AT_PB + st*9216u;
        const char* bb = smem + AT_BB + st*17408;

        uint32_t pa[4][4];
        if (isqk) {
            // S init = bias (already *log2e)
            float c[8][4];
            #pragma unroll
            for (int j=0;j<8;j++){
                float2 lo = *(const float2*)(bb + r0*272     + (j*8+c0)*4);
                float2 hi = *(const float2*)(bb + (r0+8)*272 + (j*8+c0)*4);
                c[j][0]=lo.x; c[j][1]=lo.y; c[j][2]=hi.x; c[j][3]=hi.y;
            }
            // S += Q K^T (Q pre-scaled by log2e/16)
            #pragma unroll
            for (int kt=0; kt<16; kt++){
                uint32_t qa[4];
                ldm4(qa, qaddr + kt*32);
                uint32_t kf[16];
                #pragma unroll
                for (int jp=0;jp<4;jp++)
                    ldm4(kf + jp*4, kb + (jp*16 + krow)*528 + (kt*16 + kcol)*2);
                #pragma unroll
                for (int j=0;j<8;j++)
                    mma16816(c[j], qa, kf + (j>>1)*4 + (j&1)*2);
            }
            // exp + pack (registers)
            #pragma unroll
            for (int j=0;j<8;j++){
                bool ok0 = (m0 + j*8 + c0    ) < Nv;
                bool ok1 = (m0 + j*8 + c0 + 1) < Nv;
                float p0 = ok0 ? ex2f(c[j][0]) : 0.f;
                float p1 = ok1 ? ex2f(c[j][1]) : 0.f;
                float p2 = ok0 ? ex2f(c[j][2]) : 0.f;
                float p3 = ok1 ? ex2f(c[j][3]) : 0.f;
                ls0 += p0 + p1; ls1 += p2 + p3;
                int tt = j>>1;
                if ((j&1)==0){ pa[tt][0] = packbf(p1,p0); pa[tt][1] = packbf(p3,p2); }
                else         { pa[tt][2] = packbf(p1,p0); pa[tt][3] = packbf(p3,p2); }
            }
            // publish P to smem for the dh=1 warps (conflict-free stride 144)
            uint32_t sa = pb + pst;
            #pragma unroll
            for (int tt=0;tt<4;tt++){
                sts32(sa + tt*32,            pa[tt][0]);
                sts32(sa + tt*32 + 8*144,    pa[tt][1]);
                sts32(sa + tt*32 + 16,       pa[tt][2]);
                sts32(sa + tt*32 + 8*144+16, pa[tt][3]);
            }
        }
        __syncthreads();                 // P[m&1] ready
        if (!isqk) {
            #pragma unroll
            for (int tt=0;tt<4;tt++) ldm4(pa[tt], pb + pld + tt*32);
        }
        // O += P V (this warp's 128-col D half)
        #pragma unroll
        for (int tt=0;tt<4;tt++){
            #pragma unroll
            for (int up=0;up<8;up++){
                uint32_t vf[4];
                ldm4t(vf, vb + (tt*16 + vrow)*528 + (vcol + up*16)*2);
                mma16816(o[2*up],   pa[tt], vf);
                mma16816(o[2*up+1], pa[tt], vf+2);
            }
        }
    }

    // row sums (QK warps own them) -> smem -> all warps
    if (isqk) {
        ls0 += __shfl_xor_sync(~0u, ls0, 1); ls0 += __shfl_xor_sync(~0u, ls0, 2);
        ls1 += __shfl_xor_sync(~0u, ls1, 1); ls1 += __shfl_xor_sync(~0u, ls1, 2);
        if ((lane&3)==0) {
            linv_sm[r0]   = ls0 > 0.f ? 1.f/ls0 : 0.f;
            linv_sm[r0+8] = ls1 > 0.f ? 1.f/ls1 : 0.f;
        }
    }
    __syncthreads();
    float inv0 = linv_sm[r0], inv1 = linv_sm[r0+8];

    bool rok0 = (n0 + r0)     < Nv;
    bool rok1 = (n0 + r0 + 8) < Nv;
    int gi0 = rok0 ? g_idx[n0 + r0]     : 0;
    int gi1 = rok1 ? g_idx[n0 + r0 + 8] : 0;
    __nv_bfloat16* d0 = g_cat + (size_t)gi0*(NHEAD*DIM) + h*DIM + dh*128 + c0;
    __nv_bfloat16* d1 = g_cat + (size_t)gi1*(NHEAD*DIM) + h*DIM + dh*128 + c0;
    #pragma unroll
    for (int u=0;u<16;u++){
        if (rok0) *(uint32_t*)(d0 + u*8) = packbf(o[u][1]*inv0, o[u][0]*inv0);
        if (rok1) *(uint32_t*)(d1 + u*8) = packbf(o[u][3]*inv1, o[u][2]*inv1);
    }
}

extern "C" void kernel_launch(void* const* d_in, const int* in_sizes, int n_in,
                              void* d_out, int out_size)
{
    (void)in_sizes; (void)n_in; (void)out_size;
    const float* x       = (const float*)d_in[0];
    const int*   mask    = (const int*)  d_in[1];
    const float* spatial = (const float*)d_in[2];
    const float* edge    = (const float*)d_in[3];
    const float* ln1_g   = (const float*)d_in[4];
    const float* ln1_b   = (const float*)d_in[5];
    const float* Wq = (const float*)d_in[6],  *bq = (const float*)d_in[7];
    const float* Wk = (const float*)d_in[8],  *bk = (const float*)d_in[9];
    const float* Wv = (const float*)d_in[10], *bv = (const float*)d_in[11];
    const float* Wo = (const float*)d_in[12], *bo = (const float*)d_in[13];
    const float* ln2_g = (const float*)d_in[14], *ln2_b = (const float*)d_in[15];
    const float* Wff = (const float*)d_in[16], *bff = (const float*)d_in[17];
    float* out = (float*)d_out;

    cudaFuncSetAttribute((const void*)gemm_kernel<0,1,0>, cudaFuncAttributeMaxDynamicSharedMemorySize, GEMM_SMEM);
    cudaFuncSetAttribute((const void*)gemm_kernel<1,0,1>, cudaFuncAttributeMaxDynamicSharedMemorySize, GEMM_SMEM);
    cudaFuncSetAttribute((const void*)gemm_kernel<1,0,0>, cudaFuncAttributeMaxDynamicSharedMemorySize, GEMM_SMEM);
    cudaFuncSetAttribute((const void*)attn_kernel, cudaFuncAttributeMaxDynamicSharedMemorySize, ATT_SMEM);

    __nv_bfloat16 *xln, *qkv, *cat, *xln2, *wqkv, *wo, *wff;
    float *xout;
    cudaGetSymbolAddress((void**)&xln,  g_xln);
    cudaGetSymbolAddress((void**)&wqkv, g_wqkv);
    cudaGetSymbolAddress((void**)&wo,   g_wo);
    cudaGetSymbolAddress((void**)&wff,  g_wff);
    cudaGetSymbolAddress((void**)&qkv,  g_qkv);
    cudaGetSymbolAddress((void**)&cat,  g_cat);
    cudaGetSymbolAddress((void**)&xout, g_xout);
    cudaGetSymbolAddress((void**)&xln2, g_xln2);

    compact_kernel<<<1, 1024>>>(mask);                                            // 1
    cvt_all_kernel<<<(4*HDD + DIM*DIM)/256, 256>>>(Wq, Wk, Wv, Wo, Wff);          // 2
    ln_kernel<1><<<NTOK, 256>>>(x, ln1_g, ln1_b, xln);                            // 3
    gemm_kernel<0,1,0><<<dim3(32,48), 256, GEMM_SMEM>>>(xln, wqkv, DIM,
                                                        bq, bk, bv, nullptr, nullptr, qkv); // 4
    bias_pre_kernel<<<dim3(16, NTOK), 256>>>(spatial, edge);                      // 5
    attn_kernel<<<dim3(NHEAD, NTOK/64), 256, ATT_SMEM>>>();                       // 6 (profiled)
    gemm_kernel<1,0,1><<<dim3(32,2), 256, GEMM_SMEM>>>(cat, wo, NHEAD*DIM,
                                                       bo, nullptr, nullptr, x, xout, nullptr);
    ln_kernel<0><<<NTOK, 256>>>(xout, ln2_g, ln2_b, xln2);
    gemm_kernel<1,0,0><<<dim3(32,2), 256, GEMM_SMEM>>>(xln2, wff, DIM,
                                                       bff, nullptr, nullptr, xout, out, nullptr);
}

// round 10
// speedup vs baseline: 1.5042x; 1.1026x over previous
#include <cuda_runtime.h>
#include <cuda_bf16.h>
#include <mma.h>
#include <cstdint>
using namespace nvcuda;

#define NTOK 4096
#define DIM 256
#define NHEAD 8
#define HDD (NHEAD*DIM*DIM)
#define BSTRIDE 4128
#define LOG2E 1.44269504088896f

__device__ __nv_bfloat16 g_xln [NTOK*DIM];
__device__ __nv_bfloat16 g_wqkv[3*HDD];
__device__ __nv_bfloat16 g_wo  [DIM*NHEAD*DIM];
__device__ __nv_bfloat16 g_wff [DIM*DIM];
__device__ __nv_bfloat16 g_qkv [3ULL*NHEAD*NTOK*DIM];
__device__ __nv_bfloat16 g_cat [(size_t)NTOK*NHEAD*DIM];
__device__ float         g_xout[NTOK*DIM];
__device__ __nv_bfloat16 g_xln2[NTOK*DIM];
__device__ float         g_bias[(size_t)NTOK*BSTRIDE];   // compact (sp+ed)*log2e
__device__ int g_nvalid, g_idx[NTOK], g_cidx[NTOK];

// ---- cp.async ----
__device__ __forceinline__ void cp16(void* d, const void* s) {
    uint32_t a = (uint32_t)__cvta_generic_to_shared(d);
    asm volatile("cp.async.cg.shared.global [%0], [%1], 16;\n" :: "r"(a), "l"(s));
}
__device__ __forceinline__ void cp16a(uint32_t a, const void* s) {
    asm volatile("cp.async.cg.shared.global [%0], [%1], 16;\n" :: "r"(a), "l"(s));
}
__device__ __forceinline__ void cp16p(void* d, const void* s, bool p) {
    uint32_t a = (uint32_t)__cvta_generic_to_shared(d);
    int sz = p ? 16 : 0;
    asm volatile("cp.async.cg.shared.global [%0], [%1], 16, %2;\n" :: "r"(a), "l"(s), "r"(sz));
}
__device__ __forceinline__ void cp_commit() { asm volatile("cp.async.commit_group;\n"); }
__device__ __forceinline__ void cp_wait0()  { asm volatile("cp.async.wait_group 0;\n"); }

// ---- mma.sync primitives ----
__device__ __forceinline__ void ldm4(uint32_t* r, uint32_t a) {
    asm volatile("ldmatrix.sync.aligned.m8n8.x4.shared.b16 {%0,%1,%2,%3}, [%4];"
        : "=r"(r[0]),"=r"(r[1]),"=r"(r[2]),"=r"(r[3]) : "r"(a));
}
__device__ __forceinline__ void ldm4t(uint32_t* r, uint32_t a) {
    asm volatile("ldmatrix.sync.aligned.m8n8.x4.trans.shared.b16 {%0,%1,%2,%3}, [%4];"
        : "=r"(r[0]),"=r"(r[1]),"=r"(r[2]),"=r"(r[3]) : "r"(a));
}
__device__ __forceinline__ void mma16816(float* c, const uint32_t* a, const uint32_t* b) {
    asm volatile("mma.sync.aligned.m16n8k16.row.col.f32.bf16.bf16.f32 "
        "{%0,%1,%2,%3}, {%4,%5,%6,%7}, {%8,%9}, {%0,%1,%2,%3};"
        : "+f"(c[0]),"+f"(c[1]),"+f"(c[2]),"+f"(c[3])
        : "r"(a[0]),"r"(a[1]),"r"(a[2]),"r"(a[3]), "r"(b[0]),"r"(b[1]));
}
__device__ __forceinline__ float ex2f(float x) { float y; asm("ex2.approx.ftz.f32 %0, %1;" : "=f"(y) : "f"(x)); return y; }
__device__ __forceinline__ uint32_t packbf(float hi, float lo) {
    uint32_t r; asm("cvt.rn.bf16x2.f32 %0, %1, %2;" : "=r"(r) : "f"(hi), "f"(lo)); return r;
}
__device__ __forceinline__ void sts32(uint32_t a, uint32_t v) {
    asm volatile("st.shared.u32 [%0], %1;" :: "r"(a), "r"(v) : "memory");
}

// ---- mask compaction ----
__global__ void compact_kernel(const int* __restrict__ mask)
{
    __shared__ int ws[32];
    int t = threadIdx.x, base = t*4, m[4], s = 0;
    #pragma unroll
    for (int i=0;i<4;i++){ m[i] = (mask[base+i] != 0); s += m[i]; }
    int lane = t&31, w = t>>5, pre = s;
    #pragma unroll
    for (int o=1;o<32;o<<=1){ int v = __shfl_up_sync(~0u, pre, o); if (lane >= o) pre += v; }
    if (lane == 31) ws[w] = pre;
    __syncthreads();
    if (t < 32) {
        int v = ws[t];
        #pragma unroll
        for (int o=1;o<32;o<<=1){ int u = __shfl_up_sync(~0u, v, o); if (t >= o) v += u; }
        ws[t] = v;
    }
    __syncthreads();
    int off = pre - s + ((w > 0) ? ws[w-1] : 0);
    #pragma unroll
    for (int i=0;i<4;i++){
        if (m[i]) { g_idx[off] = base+i; g_cidx[base+i] = off; off++; }
        else      g_cidx[base+i] = -1;
    }
    if (t == 0) g_nvalid = ws[31];
}

__global__ void cvt_all_kernel(const float* __restrict__ Wq, const float* __restrict__ Wk,
                               const float* __restrict__ Wv, const float* __restrict__ Wo,
                               const float* __restrict__ Wff)
{
    int i = blockIdx.x*256 + threadIdx.x;
    if      (i <   HDD) g_wqkv[i] = __float2bfloat16(Wq[i]);
    else if (i < 2*HDD) g_wqkv[i] = __float2bfloat16(Wk[i-HDD]);
    else if (i < 3*HDD) g_wqkv[i] = __float2bfloat16(Wv[i-2*HDD]);
    else if (i < 4*HDD) g_wo [i-3*HDD] = __float2bfloat16(Wo [i-3*HDD]);
    else                g_wff[i-4*HDD] = __float2bfloat16(Wff[i-4*HDD]);
}

template<int COMPACT>
__global__ void ln_kernel(const float* __restrict__ x, const float* __restrict__ g,
                          const float* __restrict__ b, __nv_bfloat16* __restrict__ out)
{
    int row = blockIdx.x, orow = row;
    if (COMPACT) { orow = g_cidx[row]; if (orow < 0) return; }
    int t = threadIdx.x;
    float v = x[row*DIM + t], sum = v, sq = v*v;
    #pragma unroll
    for (int o=16;o>0;o>>=1){ sum += __shfl_xor_sync(~0u,sum,o); sq += __shfl_xor_sync(~0u,sq,o); }
    __shared__ float s1[8], s2[8];
    if ((t&31)==0){ s1[t>>5]=sum; s2[t>>5]=sq; }
    __syncthreads();
    __shared__ float smu, srstd;
    if (t == 0) {
        float S=0, Q=0;
        #pragma unroll
        for (int i=0;i<8;i++){ S+=s1[i]; Q+=s2[i]; }
        float m = S*(1.f/DIM);
        smu = m; srstd = rsqrtf(Q*(1.f/DIM) - m*m + 1e-5f);
    }
    __syncthreads();
    out[orow*DIM + t] = __float2bfloat16((v - smu)*srstd*g[t] + b[t]);
}

// ---- compact bias precompute ----
__global__ void bias_pre_kernel(const float* __restrict__ sp, const float* __restrict__ ed)
{
    int i = blockIdx.y;
    if (i >= g_nvalid) return;
    int j = blockIdx.x*256 + threadIdx.x;
    int gi = g_idx[i];
    float v = (sp[(size_t)gi*NTOK + j] + ed[(size_t)gi*NTOK + j]) * LOG2E;
    int cj = g_cidx[j];
    if (cj >= 0) g_bias[(size_t)i*BSTRIDE + cj] = v;
}

// ---- WMMA GEMM (unchanged) ----
#define GEMM_SMEM (4*128*72*2 > 128*132*4 ? 4*128*72*2 : 128*132*4)
template<int EPI, int COMPACT, int ZMASK>
__global__ void gemm_kernel(const __nv_bfloat16* __restrict__ A, const __nv_bfloat16* __restrict__ B,
                            int K, const float* __restrict__ b0, const float* __restrict__ b1,
                            const float* __restrict__ b2, const float* __restrict__ res,
                            float* __restrict__ outf, __nv_bfloat16* __restrict__ outb)
{
    int bm = blockIdx.x * 128;
    if (COMPACT && bm >= g_nvalid) return;
    extern __shared__ char smem[];
    __nv_bfloat16* As = (__nv_bfloat16*)smem;
    __nv_bfloat16* Bs = As + 2*128*72;
    float* Cs = (float*)smem;
    int bn = blockIdx.y * 128, t = threadIdx.x, w = t>>5;
    int wr = w & 3, wc = w >> 2;
    bool pm[4];
    #pragma unroll
    for (int k=0;k<4;k++){ int r = (t + k*256) >> 3; pm[k] = !ZMASK || (g_cidx[bm+r] >= 0); }
    wmma::fragment<wmma::accumulator,16,16,16,float> acc[2][4];
    #pragma unroll
    for (int i=0;i<2;i++)
        #pragma unroll
        for (int j=0;j<4;j++) wmma::fill_fragment(acc[i][j], 0.f);
    int nP = K >> 6;
    auto pref = [&](int p, int st){
        const __nv_bfloat16* Ap = A + (size_t)bm*K + p*64;
        const __nv_bfloat16* Bp = B + (size_t)bn*K + p*64;
        __nv_bfloat16* Ad = As + st*128*72;
        __nv_bfloat16* Bd = Bs + st*128*72;
        #pragma unroll
        for (int k=0;k<4;k++){
            int id = t + k*256, r = id>>3, c = (id&7)<<3;
            cp16p(Ad + r*72 + c, Ap + (size_t)r*K + c, pm[k]);
            cp16 (Bd + r*72 + c, Bp + (size_t)r*K + c);
        }
        cp_commit();
    };
    pref(0, 0);
    for (int p=0;p<nP;p++){
        cp_wait0(); __syncthreads();
        if (p+1 < nP) pref(p+1, (p+1)&1);
        int st = p & 1;
        __nv_bfloat16* Ad = As + st*128*72;
        __nv_bfloat16* Bd = Bs + st*128*72;
        #pragma unroll
        for (int kk=0;kk<4;kk++){
            wmma::fragment<wmma::matrix_a,16,16,16,__nv_bfloat16,wmma::row_major> af[2];
            #pragma unroll
            for (int i=0;i<2;i++) wmma::load_matrix_sync(af[i], Ad + (wr*32+i*16)*72 + kk*16, 72);
            #pragma unroll
            for (int j=0;j<4;j++){
                wmma::fragment<wmma::matrix_b,16,16,16,__nv_bfloat16,wmma::col_major> bf;
                wmma::load_matrix_sync(bf, Bd + (wc*64+j*16)*72 + kk*16, 72);
                #pragma unroll
                for (int i=0;i<2;i++) wmma::mma_sync(acc[i][j], af[i], bf, acc[i][j]);
            }
        }
        __syncthreads();
    }
    #pragma unroll
    for (int i=0;i<2;i++)
        #pragma unroll
        for (int j=0;j<4;j++)
            wmma::store_matrix_sync(&Cs[(wr*32+i*16)*132 + wc*64 + j*16], acc[i][j], 132, wmma::mem_row_major);
    __syncthreads();
    for (int idx=t; idx<128*128; idx+=256){
        int r = idx>>7, c = idx&127, n = bm+r, cc = bn+c;
        float v = Cs[r*132 + c];
        if (EPI == 0) {
            int which = cc >> 11;
            const float* bp = (which==0) ? b0 : (which==1) ? b1 : b2;
            v += bp[cc & 2047];
            if (which == 0) v *= 0.0625f*LOG2E;
            int h = (cc>>8)&7, e = cc&255;
            outb[((size_t)which*NHEAD + h)*NTOK*DIM + (size_t)n*DIM + e] = __float2bfloat16(v);
        } else {
            v += b0[cc] + res[(size_t)n*DIM + cc];
            outf[(size_t)n*DIM + cc] = v;
        }
    }
}

// ---- FA2 attention, BN=32, swizzled tiles, 2 CTAs/SM ----
// smem: Q 64x512(sw) @0 | K 2x(32x512 sw) @32768 | V 2x(32x512 sw) @65536 |
//       P 64x80 @98304 | bias 64x144 @103424 | linv @112640 ; total 112896
#define AT_K 32768
#define AT_V 65536
#define AT_P 98304
#define AT_B 103424
#define AT_L 112640
#define ATT_SMEM 112896

__global__ void __launch_bounds__(256,2) attn_kernel()
{
    int Nv = g_nvalid;
    int h = blockIdx.x, n0 = blockIdx.y*64;
    if (n0 >= Nv) return;
    extern __shared__ char smem[];
    uint32_t sb = (uint32_t)__cvta_generic_to_shared(smem);
    float* linv_sm = (float*)(smem + AT_L);
    int t = threadIdx.x, lane = t&31, w = t>>5;
    int g2 = w & 3, dh = w >> 2;
    bool isqk = (w < 4);
    int x7 = lane & 7;                      // swizzle phase for all our row patterns

    const __nv_bfloat16* qh = g_qkv + (size_t)h*NTOK*DIM;
    const __nv_bfloat16* kh = g_qkv + (size_t)(NHEAD+h)*NTOK*DIM;
    const __nv_bfloat16* vh = g_qkv + (size_t)(2*NHEAD+h)*NTOK*DIM;

    auto pref_kv = [&](int m){
        int st = m&1, m0 = m<<5;
        uint32_t kb = sb + AT_K + st*16384u;
        uint32_t vb = sb + AT_V + st*16384u;
        #pragma unroll
        for (int i=0;i<4;i++){
            int id = t + i*256, r = id>>5, c = id&31;
            uint32_t sw = ((uint32_t)r<<9) + (uint32_t)((c ^ (r&7))<<4);
            cp16a(kb + sw, kh + (size_t)(m0+r)*DIM + c*8);
            cp16a(vb + sw, vh + (size_t)(m0+r)*DIM + c*8);
        }
        cp_commit();
    };
    auto pref_b = [&](int m){
        int m0 = m<<5;
        #pragma unroll
        for (int i=0;i<2;i++){
            int id = t + i*256, r = id>>3, c = id&7;
            cp16a(sb + AT_B + r*144 + c*16, g_bias + (size_t)(n0+r)*BSTRIDE + m0 + c*4);
        }
        cp_commit();
    };

    // stage Q (swizzled) + first K/V + first bias
    #pragma unroll
    for (int i=0;i<8;i++){
        int id = t + i*256, r = id>>5, c = id&31;
        uint32_t sw = ((uint32_t)r<<9) + (uint32_t)((c ^ (r&7))<<4);
        cp16a(sb + sw, qh + (size_t)(n0+r)*DIM + c*8);
    }
    pref_kv(0);
    pref_b(0);

    // per-lane geometry
    int sub = lane>>3;
    int qrow = g2*16 + (lane&15);
    int qch0 = lane>>4;                       // chunk offset within kt pair
    int krow = ((sub>>1)<<3) + (lane&7);      // 16 rows per jp
    int kch0 = sub&1;
    int vrow = ((sub&1)<<3) + (lane&7);
    int vch0 = (dh<<4) + (sub>>1);
    int r0 = g2*16 + (lane>>2);
    int c0 = (lane&3)*2;
    uint32_t pst = (uint32_t)(r0*80 + c0*2);
    uint32_t pld = (uint32_t)((g2*16 + (lane&15))*80 + ((lane>>4)<<4));

    float o[16][4];
    #pragma unroll
    for (int u=0;u<16;u++){ o[u][0]=0;o[u][1]=0;o[u][2]=0;o[u][3]=0; }
    float ls0 = 0.f, ls1 = 0.f;
    int T = (Nv + 31) >> 5;

    for (int m=0; m<T; m++){
        cp_wait0();
        __syncthreads();                       // K/V[m], bias[m] ready; P free
        if (m+1 < T) pref_kv(m+1);
        int st = m&1, m0 = m<<5;
        uint32_t kb = sb + AT_K + st*16384u;
        uint32_t vb = sb + AT_V + st*16384u;
        const char* bbp = smem + AT_B;

        uint32_t pa[2][4];
        if (isqk) {
            float c4[4][4];
            #pragma unroll
            for (int j=0;j<4;j++){
                float2 lo = *(const float2*)(bbp + r0*144     + (j*8+c0)*4);
                float2 hi = *(const float2*)(bbp + (r0+8)*144 + (j*8+c0)*4);
                c4[j][0]=lo.x; c4[j][1]=lo.y; c4[j][2]=hi.x; c4[j][3]=hi.y;
            }
            #pragma unroll
            for (int kt=0; kt<16; kt++){
                uint32_t qa[4];
                ldm4(qa, sb + ((uint32_t)qrow<<9) + (uint32_t)(((2*kt + qch0) ^ x7)<<4));
                uint32_t kf[8];
                #pragma unroll
                for (int jp=0;jp<2;jp++){
                    int krr = jp*16 + krow;
                    ldm4(kf + jp*4, kb + ((uint32_t)krr<<9) + (uint32_t)(((2*kt + kch0) ^ x7)<<4));
                }
                #pragma unroll
                for (int j=0;j<4;j++)
                    mma16816(c4[j], qa, kf + (j>>1)*4 + (j&1)*2);
            }
            #pragma unroll
            for (int j=0;j<4;j++){
                bool ok0 = (m0 + j*8 + c0    ) < Nv;
                bool ok1 = (m0 + j*8 + c0 + 1) < Nv;
                float p0 = ok0 ? ex2f(c4[j][0]) : 0.f;
                float p1 = ok1 ? ex2f(c4[j][1]) : 0.f;
                float p2 = ok0 ? ex2f(c4[j][2]) : 0.f;
                float p3 = ok1 ? ex2f(c4[j][3]) : 0.f;
                ls0 += p0 + p1; ls1 += p2 + p3;
                int tt = j>>1;
                if ((j&1)==0){ pa[tt][0] = packbf(p1,p0); pa[tt][1] = packbf(p3,p2); }
                else         { pa[tt][2] = packbf(p1,p0); pa[tt][3] = packbf(p3,p2); }
            }
            uint32_t sa = sb + AT_P + pst;
            #pragma unroll
            for (int tt=0;tt<2;tt++){
                sts32(sa + tt*32,           pa[tt][0]);
                sts32(sa + tt*32 + 8*80,    pa[tt][1]);
                sts32(sa + tt*32 + 16,      pa[tt][2]);
                sts32(sa + tt*32 + 8*80+16, pa[tt][3]);
            }
        }
        __syncthreads();                       // P ready; bias[m] consumed
        if (m+1 < T) pref_b(m+1);
        if (!isqk) {
            #pragma unroll
            for (int tt=0;tt<2;tt++) ldm4(pa[tt], sb + AT_P + pld + tt*32);
        }
        #pragma unroll
        for (int tt=0;tt<2;tt++){
            #pragma unroll
            for (int up=0;up<8;up++){
                int vr = tt*16 + vrow;
                uint32_t vf[4];
                ldm4t(vf, vb + ((uint32_t)vr<<9) + (uint32_t)(((vch0 + up*2) ^ x7)<<4));
                mma16816(o[2*up],   pa[tt], vf);
                mma16816(o[2*up+1], pa[tt], vf+2);
            }
        }
    }

    if (isqk) {
        ls0 += __shfl_xor_sync(~0u, ls0, 1); ls0 += __shfl_xor_sync(~0u, ls0, 2);
        ls1 += __shfl_xor_sync(~0u, ls1, 1); ls1 += __shfl_xor_sync(~0u, ls1, 2);
        if ((lane&3)==0) {
            linv_sm[r0]   = ls0 > 0.f ? 1.f/ls0 : 0.f;
            linv_sm[r0+8] = ls1 > 0.f ? 1.f/ls1 : 0.f;
        }
    }
    __syncthreads();
    float inv0 = linv_sm[r0], inv1 = linv_sm[r0+8];

    bool rok0 = (n0 + r0)     < Nv;
    bool rok1 = (n0 + r0 + 8) < Nv;
    int gi0 = rok0 ? g_idx[n0 + r0]     : 0;
    int gi1 = rok1 ? g_idx[n0 + r0 + 8] : 0;
    __nv_bfloat16* d0 = g_cat + (size_t)gi0*(NHEAD*DIM) + h*DIM + dh*128 + c0;
    __nv_bfloat16* d1 = g_cat + (size_t)gi1*(NHEAD*DIM) + h*DIM + dh*128 + c0;
    #pragma unroll
    for (int u=0;u<16;u++){
        if (rok0) *(uint32_t*)(d0 + u*8) = packbf(o[u][1]*inv0, o[u][0]*inv0);
        if (rok1) *(uint32_t*)(d1 + u*8) = packbf(o[u][3]*inv1, o[u][2]*inv1);
    }
}

extern "C" void kernel_launch(void* const* d_in, const int* in_sizes, int n_in,
                              void* d_out, int out_size)
{
    (void)in_sizes; (void)n_in; (void)out_size;
    const float* x       = (const float*)d_in[0];
    const int*   mask    = (const int*)  d_in[1];
    const float* spatial = (const float*)d_in[2];
    const float* edge    = (const float*)d_in[3];
    const float* ln1_g   = (const float*)d_in[4];
    const float* ln1_b   = (const float*)d_in[5];
    const float* Wq = (const float*)d_in[6],  *bq = (const float*)d_in[7];
    const float* Wk = (const float*)d_in[8],  *bk = (const float*)d_in[9];
    const float* Wv = (const float*)d_in[10], *bv = (const float*)d_in[11];
    const float* Wo = (const float*)d_in[12], *bo = (const float*)d_in[13];
    const float* ln2_g = (const float*)d_in[14], *ln2_b = (const float*)d_in[15];
    const float* Wff = (const float*)d_in[16], *bff = (const float*)d_in[17];
    float* out = (float*)d_out;

    cudaFuncSetAttribute((const void*)gemm_kernel<0,1,0>, cudaFuncAttributeMaxDynamicSharedMemorySize, GEMM_SMEM);
    cudaFuncSetAttribute((const void*)gemm_kernel<1,0,1>, cudaFuncAttributeMaxDynamicSharedMemorySize, GEMM_SMEM);
    cudaFuncSetAttribute((const void*)gemm_kernel<1,0,0>, cudaFuncAttributeMaxDynamicSharedMemorySize, GEMM_SMEM);
    cudaFuncSetAttribute((const void*)attn_kernel, cudaFuncAttributeMaxDynamicSharedMemorySize, ATT_SMEM);

    __nv_bfloat16 *xln, *qkv, *cat, *xln2, *wqkv, *wo, *wff;
    float *xout;
    cudaGetSymbolAddress((void**)&xln,  g_xln);
    cudaGetSymbolAddress((void**)&wqkv, g_wqkv);
    cudaGetSymbolAddress((void**)&wo,   g_wo);
    cudaGetSymbolAddress((void**)&wff,  g_wff);
    cudaGetSymbolAddress((void**)&qkv,  g_qkv);
    cudaGetSymbolAddress((void**)&cat,  g_cat);
    cudaGetSymbolAddress((void**)&xout, g_xout);
    cudaGetSymbolAddress((void**)&xln2, g_xln2);

    compact_kernel<<<1, 1024>>>(mask);                                            // 1
    cvt_all_kernel<<<(4*HDD + DIM*DIM)/256, 256>>>(Wq, Wk, Wv, Wo, Wff);          // 2
    ln_kernel<1><<<NTOK, 256>>>(x, ln1_g, ln1_b, xln);                            // 3
    gemm_kernel<0,1,0><<<dim3(32,48), 256, GEMM_SMEM>>>(xln, wqkv, DIM,
                                                        bq, bk, bv, nullptr, nullptr, qkv); // 4
    bias_pre_kernel<<<dim3(16, NTOK), 256>>>(spatial, edge);                      // 5
    attn_kernel<<<dim3(NHEAD, NTOK/64), 256, ATT_SMEM>>>();                       // 6 (profiled)
    gemm_kernel<1,0,1><<<dim3(32,2), 256, GEMM_SMEM>>>(cat, wo, NHEAD*DIM,
                                                       bo, nullptr, nullptr, x, xout, nullptr);
    ln_kernel<0><<<NTOK, 256>>>(xout, ln2_g, ln2_b, xln2);
    gemm_kernel<1,0,0><<<dim3(32,2), 256, GEMM_SMEM>>>(xln2, wff, DIM,
                                                       bff, nullptr, nullptr, xout, out, nullptr);
}

// round 11
// speedup vs baseline: 1.6827x; 1.1187x over previous
#include <cuda_runtime.h>
#include <cuda_bf16.h>
#include <mma.h>
#include <cstdint>
using namespace nvcuda;

#define NTOK 4096
#define DIM 256
#define NHEAD 8
#define HDD (NHEAD*DIM*DIM)
#define BSTRIDE 4128
#define LOG2E 1.44269504088896f

__device__ __nv_bfloat16 g_xln [NTOK*DIM];
__device__ __nv_bfloat16 g_wqkv[3*HDD];
__device__ __nv_bfloat16 g_wo  [DIM*NHEAD*DIM];
__device__ __nv_bfloat16 g_wff [DIM*DIM];
__device__ __nv_bfloat16 g_qkv [3ULL*NHEAD*NTOK*DIM];
__device__ __nv_bfloat16 g_cat [(size_t)NTOK*NHEAD*DIM];
__device__ float         g_xout[NTOK*DIM];
__device__ __nv_bfloat16 g_xln2[NTOK*DIM];
__device__ float         g_bias[(size_t)NTOK*BSTRIDE];   // compact (sp+ed)*log2e
__device__ int g_nvalid, g_idx[NTOK], g_cidx[NTOK];

// ---- cp.async ----
__device__ __forceinline__ void cp16a(uint32_t a, const void* s) {
    asm volatile("cp.async.cg.shared.global [%0], [%1], 16;\n" :: "r"(a), "l"(s));
}
__device__ __forceinline__ void cp16p(void* d, const void* s, bool p) {
    uint32_t a = (uint32_t)__cvta_generic_to_shared(d);
    int sz = p ? 16 : 0;
    asm volatile("cp.async.cg.shared.global [%0], [%1], 16, %2;\n" :: "r"(a), "l"(s), "r"(sz));
}
__device__ __forceinline__ void cp16(void* d, const void* s) {
    uint32_t a = (uint32_t)__cvta_generic_to_shared(d);
    asm volatile("cp.async.cg.shared.global [%0], [%1], 16;\n" :: "r"(a), "l"(s));
}
__device__ __forceinline__ void cp_commit() { asm volatile("cp.async.commit_group;\n"); }
__device__ __forceinline__ void cp_wait0()  { asm volatile("cp.async.wait_group 0;\n"); }

// ---- mma.sync primitives ----
__device__ __forceinline__ void ldm4(uint32_t* r, uint32_t a) {
    asm volatile("ldmatrix.sync.aligned.m8n8.x4.shared.b16 {%0,%1,%2,%3}, [%4];"
        : "=r"(r[0]),"=r"(r[1]),"=r"(r[2]),"=r"(r[3]) : "r"(a));
}
__device__ __forceinline__ void ldm4t(uint32_t* r, uint32_t a) {
    asm volatile("ldmatrix.sync.aligned.m8n8.x4.trans.shared.b16 {%0,%1,%2,%3}, [%4];"
        : "=r"(r[0]),"=r"(r[1]),"=r"(r[2]),"=r"(r[3]) : "r"(a));
}
__device__ __forceinline__ void mma16816(float* c, const uint32_t* a, const uint32_t* b) {
    asm volatile("mma.sync.aligned.m16n8k16.row.col.f32.bf16.bf16.f32 "
        "{%0,%1,%2,%3}, {%4,%5,%6,%7}, {%8,%9}, {%0,%1,%2,%3};"
        : "+f"(c[0]),"+f"(c[1]),"+f"(c[2]),"+f"(c[3])
        : "r"(a[0]),"r"(a[1]),"r"(a[2]),"r"(a[3]), "r"(b[0]),"r"(b[1]));
}
__device__ __forceinline__ float ex2f(float x) { float y; asm("ex2.approx.ftz.f32 %0, %1;" : "=f"(y) : "f"(x)); return y; }
__device__ __forceinline__ uint32_t packbf(float hi, float lo) {
    uint32_t r; asm("cvt.rn.bf16x2.f32 %0, %1, %2;" : "=r"(r) : "f"(hi), "f"(lo)); return r;
}
__device__ __forceinline__ void sts32(uint32_t a, uint32_t v) {
    asm volatile("st.shared.u32 [%0], %1;" :: "r"(a), "r"(v) : "memory");
}

// ---- mask compaction ----
__global__ void compact_kernel(const int* __restrict__ mask)
{
    __shared__ int ws[32];
    int t = threadIdx.x, base = t*4, m[4], s = 0;
    #pragma unroll
    for (int i=0;i<4;i++){ m[i] = (mask[base+i] != 0); s += m[i]; }
    int lane = t&31, w = t>>5, pre = s;
    #pragma unroll
    for (int o=1;o<32;o<<=1){ int v = __shfl_up_sync(~0u, pre, o); if (lane >= o) pre += v; }
    if (lane == 31) ws[w] = pre;
    __syncthreads();
    if (t < 32) {
        int v = ws[t];
        #pragma unroll
        for (int o=1;o<32;o<<=1){ int u = __shfl_up_sync(~0u, v, o); if (t >= o) v += u; }
        ws[t] = v;
    }
    __syncthreads();
    int off = pre - s + ((w > 0) ? ws[w-1] : 0);
    #pragma unroll
    for (int i=0;i<4;i++){
        if (m[i]) { g_idx[off] = base+i; g_cidx[base+i] = off; off++; }
        else      g_cidx[base+i] = -1;
    }
    if (t == 0) g_nvalid = ws[31];
}

__global__ void cvt_all_kernel(const float* __restrict__ Wq, const float* __restrict__ Wk,
                               const float* __restrict__ Wv, const float* __restrict__ Wo,
                               const float* __restrict__ Wff)
{
    int i = blockIdx.x*256 + threadIdx.x;
    if      (i <   HDD) g_wqkv[i] = __float2bfloat16(Wq[i]);
    else if (i < 2*HDD) g_wqkv[i] = __float2bfloat16(Wk[i-HDD]);
    else if (i < 3*HDD) g_wqkv[i] = __float2bfloat16(Wv[i-2*HDD]);
    else if (i < 4*HDD) g_wo [i-3*HDD] = __float2bfloat16(Wo [i-3*HDD]);
    else                g_wff[i-4*HDD] = __float2bfloat16(Wff[i-4*HDD]);
}

template<int COMPACT>
__global__ void ln_kernel(const float* __restrict__ x, const float* __restrict__ g,
                          const float* __restrict__ b, __nv_bfloat16* __restrict__ out)
{
    int row = blockIdx.x, orow = row;
    if (COMPACT) { orow = g_cidx[row]; if (orow < 0) return; }
    int t = threadIdx.x;
    float v = x[row*DIM + t], sum = v, sq = v*v;
    #pragma unroll
    for (int o=16;o>0;o>>=1){ sum += __shfl_xor_sync(~0u,sum,o); sq += __shfl_xor_sync(~0u,sq,o); }
    __shared__ float s1[8], s2[8];
    if ((t&31)==0){ s1[t>>5]=sum; s2[t>>5]=sq; }
    __syncthreads();
    __shared__ float smu, srstd;
    if (t == 0) {
        float S=0, Q=0;
        #pragma unroll
        for (int i=0;i<8;i++){ S+=s1[i]; Q+=s2[i]; }
        float m = S*(1.f/DIM);
        smu = m; srstd = rsqrtf(Q*(1.f/DIM) - m*m + 1e-5f);
    }
    __syncthreads();
    out[orow*DIM + t] = __float2bfloat16((v - smu)*srstd*g[t] + b[t]);
}

// ---- compact bias precompute: float4 vectorized ----
__global__ void bias_pre_kernel(const float* __restrict__ sp, const float* __restrict__ ed)
{
    int i = blockIdx.y;
    if (i >= g_nvalid) return;
    int j = (blockIdx.x*256 + threadIdx.x)*4;
    int gi = g_idx[i];
    float4 s4 = *(const float4*)(sp + (size_t)gi*NTOK + j);
    float4 e4 = *(const float4*)(ed + (size_t)gi*NTOK + j);
    float* brow = g_bias + (size_t)i*BSTRIDE;
    int c0 = g_cidx[j], c1 = g_cidx[j+1], c2 = g_cidx[j+2], c3 = g_cidx[j+3];
    if (c0 >= 0) brow[c0] = (s4.x + e4.x)*LOG2E;
    if (c1 >= 0) brow[c1] = (s4.y + e4.y)*LOG2E;
    if (c2 >= 0) brow[c2] = (s4.z + e4.z)*LOG2E;
    if (c3 >= 0) brow[c3] = (s4.w + e4.w)*LOG2E;
}

// ---- WMMA GEMM, templated tile-M ----
#define GEMM_SMEM 73728
template<int EPI, int COMPACT, int ZMASK, int TM>
__global__ void gemm_kernel(const __nv_bfloat16* __restrict__ A, const __nv_bfloat16* __restrict__ B,
                            int K, const float* __restrict__ b0, const float* __restrict__ b1,
                            const float* __restrict__ b2, const float* __restrict__ res,
                            float* __restrict__ outf, __nv_bfloat16* __restrict__ outb)
{
    constexpr int MI = TM/64;        // m16 tiles per warp
    constexpr int NCH = TM/32;       // A chunks per thread per panel
    int bm = blockIdx.x * TM;
    if (COMPACT && bm >= g_nvalid) return;
    extern __shared__ char smem[];
    __nv_bfloat16* As = (__nv_bfloat16*)smem;
    __nv_bfloat16* Bs = As + 2*TM*72;
    float* Cs = (float*)smem;
    int bn = blockIdx.y * 128, t = threadIdx.x, w = t>>5;
    int wr = w & 3, wc = w >> 2;
    bool pm[NCH];
    #pragma unroll
    for (int k=0;k<NCH;k++){ int r = (t + k*256) >> 3; pm[k] = !ZMASK || (g_cidx[bm+r] >= 0); }
    wmma::fragment<wmma::accumulator,16,16,16,float> acc[MI][4];
    #pragma unroll
    for (int i=0;i<MI;i++)
        #pragma unroll
        for (int j=0;j<4;j++) wmma::fill_fragment(acc[i][j], 0.f);
    int nP = K >> 6;
    auto pref = [&](int p, int st){
        const __nv_bfloat16* Ap = A + (size_t)bm*K + p*64;
        const __nv_bfloat16* Bp = B + (size_t)bn*K + p*64;
        __nv_bfloat16* Ad = As + st*TM*72;
        __nv_bfloat16* Bd = Bs + st*128*72;
        #pragma unroll
        for (int k=0;k<NCH;k++){
            int id = t + k*256, r = id>>3, c = (id&7)<<3;
            cp16p(Ad + r*72 + c, Ap + (size_t)r*K + c, pm[k]);
        }
        #pragma unroll
        for (int k=0;k<4;k++){
            int id = t + k*256, r = id>>3, c = (id&7)<<3;
            cp16 (Bd + r*72 + c, Bp + (size_t)r*K + c);
        }
        cp_commit();
    };
    pref(0, 0);
    for (int p=0;p<nP;p++){
        cp_wait0(); __syncthreads();
        if (p+1 < nP) pref(p+1, (p+1)&1);
        int st = p & 1;
        __nv_bfloat16* Ad = As + st*TM*72;
        __nv_bfloat16* Bd = Bs + st*128*72;
        #pragma unroll
        for (int kk=0;kk<4;kk++){
            wmma::fragment<wmma::matrix_a,16,16,16,__nv_bfloat16,wmma::row_major> af[MI];
            #pragma unroll
            for (int i=0;i<MI;i++) wmma::load_matrix_sync(af[i], Ad + (wr*(TM/4)+i*16)*72 + kk*16, 72);
            #pragma unroll
            for (int j=0;j<4;j++){
                wmma::fragment<wmma::matrix_b,16,16,16,__nv_bfloat16,wmma::col_major> bf;
                wmma::load_matrix_sync(bf, Bd + (wc*64+j*16)*72 + kk*16, 72);
                #pragma unroll
                for (int i=0;i<MI;i++) wmma::mma_sync(acc[i][j], af[i], bf, acc[i][j]);
            }
        }
        __syncthreads();
    }
    #pragma unroll
    for (int i=0;i<MI;i++)
        #pragma unroll
        for (int j=0;j<4;j++)
            wmma::store_matrix_sync(&Cs[(wr*(TM/4)+i*16)*132 + wc*64 + j*16], acc[i][j], 132, wmma::mem_row_major);
    __syncthreads();
    for (int idx=t; idx<TM*128; idx+=256){
        int r = idx>>7, c = idx&127, n = bm+r, cc = bn+c;
        float v = Cs[r*132 + c];
        if (EPI == 0) {
            int which = cc >> 11;
            const float* bp = (which==0) ? b0 : (which==1) ? b1 : b2;
            v += bp[cc & 2047];
            if (which == 0) v *= 0.0625f*LOG2E;
            int h = (cc>>8)&7, e = cc&255;
            outb[((size_t)which*NHEAD + h)*NTOK*DIM + (size_t)n*DIM + e] = __float2bfloat16(v);
        } else {
            v += b0[cc] + res[(size_t)n*DIM + cc];
            outf[(size_t)n*DIM + cc] = v;
        }
    }
}

// ---- FA2 attention, BN=32, swizzled tiles, 2 CTAs/SM (round-10, unchanged) ----
#define AT_K 32768
#define AT_V 65536
#define AT_P 98304
#define AT_B 103424
#define AT_L 112640
#define ATT_SMEM 112896

__global__ void __launch_bounds__(256,2) attn_kernel()
{
    int Nv = g_nvalid;
    int h = blockIdx.x, n0 = blockIdx.y*64;
    if (n0 >= Nv) return;
    extern __shared__ char smem[];
    uint32_t sb = (uint32_t)__cvta_generic_to_shared(smem);
    float* linv_sm = (float*)(smem + AT_L);
    int t = threadIdx.x, lane = t&31, w = t>>5;
    int g2 = w & 3, dh = w >> 2;
    bool isqk = (w < 4);
    int x7 = lane & 7;

    const __nv_bfloat16* qh = g_qkv + (size_t)h*NTOK*DIM;
    const __nv_bfloat16* kh = g_qkv + (size_t)(NHEAD+h)*NTOK*DIM;
    const __nv_bfloat16* vh = g_qkv + (size_t)(2*NHEAD+h)*NTOK*DIM;

    auto pref_kv = [&](int m){
        int st = m&1, m0 = m<<5;
        uint32_t kb = sb + AT_K + st*16384u;
        uint32_t vb = sb + AT_V + st*16384u;
        #pragma unroll
        for (int i=0;i<4;i++){
            int id = t + i*256, r = id>>5, c = id&31;
            uint32_t sw = ((uint32_t)r<<9) + (uint32_t)((c ^ (r&7))<<4);
            cp16a(kb + sw, kh + (size_t)(m0+r)*DIM + c*8);
            cp16a(vb + sw, vh + (size_t)(m0+r)*DIM + c*8);
        }
        cp_commit();
    };
    auto pref_b = [&](int m){
        int m0 = m<<5;
        #pragma unroll
        for (int i=0;i<2;i++){
            int id = t + i*256, r = id>>3, c = id&7;
            cp16a(sb + AT_B + r*144 + c*16, g_bias + (size_t)(n0+r)*BSTRIDE + m0 + c*4);
        }
        cp_commit();
    };

    #pragma unroll
    for (int i=0;i<8;i++){
        int id = t + i*256, r = id>>5, c = id&31;
        uint32_t sw = ((uint32_t)r<<9) + (uint32_t)((c ^ (r&7))<<4);
        cp16a(sb + sw, qh + (size_t)(n0+r)*DIM + c*8);
    }
    pref_kv(0);
    pref_b(0);

    int sub = lane>>3;
    int qrow = g2*16 + (lane&15);
    int qch0 = lane>>4;
    int krow = ((sub>>1)<<3) + (lane&7);
    int kch0 = sub&1;
    int vrow = ((sub&1)<<3) + (lane&7);
    int vch0 = (dh<<4) + (sub>>1);
    int r0 = g2*16 + (lane>>2);
    int c0 = (lane&3)*2;
    uint32_t pst = (uint32_t)(r0*80 + c0*2);
    uint32_t pld = (uint32_t)((g2*16 + (lane&15))*80 + ((lane>>4)<<4));

    float o[16][4];
    #pragma unroll
    for (int u=0;u<16;u++){ o[u][0]=0;o[u][1]=0;o[u][2]=0;o[u][3]=0; }
    float ls0 = 0.f, ls1 = 0.f;
    int T = (Nv + 31) >> 5;

    for (int m=0; m<T; m++){
        cp_wait0();
        __syncthreads();
        if (m+1 < T) pref_kv(m+1);
        int st = m&1, m0 = m<<5;
        uint32_t kb = sb + AT_K + st*16384u;
        uint32_t vb = sb + AT_V + st*16384u;
        const char* bbp = smem + AT_B;

        uint32_t pa[2][4];
        if (isqk) {
            float c4[4][4];
            #pragma unroll
            for (int j=0;j<4;j++){
                float2 lo = *(const float2*)(bbp + r0*144     + (j*8+c0)*4);
                float2 hi = *(const float2*)(bbp + (r0+8)*144 + (j*8+c0)*4);
                c4[j][0]=lo.x; c4[j][1]=lo.y; c4[j][2]=hi.x; c4[j][3]=hi.y;
            }
            #pragma unroll
            for (int kt=0; kt<16; kt++){
                uint32_t qa[4];
                ldm4(qa, sb + ((uint32_t)qrow<<9) + (uint32_t)(((2*kt + qch0) ^ x7)<<4));
                uint32_t kf[8];
                #pragma unroll
                for (int jp=0;jp<2;jp++){
                    int krr = jp*16 + krow;
                    ldm4(kf + jp*4, kb + ((uint32_t)krr<<9) + (uint32_t)(((2*kt + kch0) ^ x7)<<4));
                }
                #pragma unroll
                for (int j=0;j<4;j++)
                    mma16816(c4[j], qa, kf + (j>>1)*4 + (j&1)*2);
            }
            #pragma unroll
            for (int j=0;j<4;j++){
                bool ok0 = (m0 + j*8 + c0    ) < Nv;
                bool ok1 = (m0 + j*8 + c0 + 1) < Nv;
                float p0 = ok0 ? ex2f(c4[j][0]) : 0.f;
                float p1 = ok1 ? ex2f(c4[j][1]) : 0.f;
                float p2 = ok0 ? ex2f(c4[j][2]) : 0.f;
                float p3 = ok1 ? ex2f(c4[j][3]) : 0.f;
                ls0 += p0 + p1; ls1 += p2 + p3;
                int tt = j>>1;
                if ((j&1)==0){ pa[tt][0] = packbf(p1,p0); pa[tt][1] = packbf(p3,p2); }
                else         { pa[tt][2] = packbf(p1,p0); pa[tt][3] = packbf(p3,p2); }
            }
            uint32_t sa = sb + AT_P + pst;
            #pragma unroll
            for (int tt=0;tt<2;tt++){
                sts32(sa + tt*32,           pa[tt][0]);
                sts32(sa + tt*32 + 8*80,    pa[tt][1]);
                sts32(sa + tt*32 + 16,      pa[tt][2]);
                sts32(sa + tt*32 + 8*80+16, pa[tt][3]);
            }
        }
        __syncthreads();
        if (m+1 < T) pref_b(m+1);
        if (!isqk) {
            #pragma unroll
            for (int tt=0;tt<2;tt++) ldm4(pa[tt], sb + AT_P + pld + tt*32);
        }
        #pragma unroll
        for (int tt=0;tt<2;tt++){
            #pragma unroll
            for (int up=0;up<8;up++){
                int vr = tt*16 + vrow;
                uint32_t vf[4];
                ldm4t(vf, vb + ((uint32_t)vr<<9) + (uint32_t)(((vch0 + up*2) ^ x7)<<4));
                mma16816(o[2*up],   pa[tt], vf);
                mma16816(o[2*up+1], pa[tt], vf+2);
            }
        }
    }

    if (isqk) {
        ls0 += __shfl_xor_sync(~0u, ls0, 1); ls0 += __shfl_xor_sync(~0u, ls0, 2);
        ls1 += __shfl_xor_sync(~0u, ls1, 1); ls1 += __shfl_xor_sync(~0u, ls1, 2);
        if ((lane&3)==0) {
            linv_sm[r0]   = ls0 > 0.f ? 1.f/ls0 : 0.f;
            linv_sm[r0+8] = ls1 > 0.f ? 1.f/ls1 : 0.f;
        }
    }
    __syncthreads();
    float inv0 = linv_sm[r0], inv1 = linv_sm[r0+8];

    bool rok0 = (n0 + r0)     < Nv;
    bool rok1 = (n0 + r0 + 8) < Nv;
    int gi0 = rok0 ? g_idx[n0 + r0]     : 0;
    int gi1 = rok1 ? g_idx[n0 + r0 + 8] : 0;
    __nv_bfloat16* d0 = g_cat + (size_t)gi0*(NHEAD*DIM) + h*DIM + dh*128 + c0;
    __nv_bfloat16* d1 = g_cat + (size_t)gi1*(NHEAD*DIM) + h*DIM + dh*128 + c0;
    #pragma unroll
    for (int u=0;u<16;u++){
        if (rok0) *(uint32_t*)(d0 + u*8) = packbf(o[u][1]*inv0, o[u][0]*inv0);
        if (rok1) *(uint32_t*)(d1 + u*8) = packbf(o[u][3]*inv1, o[u][2]*inv1);
    }
}

extern "C" void kernel_launch(void* const* d_in, const int* in_sizes, int n_in,
                              void* d_out, int out_size)
{
    (void)in_sizes; (void)n_in; (void)out_size;
    const float* x       = (const float*)d_in[0];
    const int*   mask    = (const int*)  d_in[1];
    const float* spatial = (const float*)d_in[2];
    const float* edge    = (const float*)d_in[3];
    const float* ln1_g   = (const float*)d_in[4];
    const float* ln1_b   = (const float*)d_in[5];
    const float* Wq = (const float*)d_in[6],  *bq = (const float*)d_in[7];
    const float* Wk = (const float*)d_in[8],  *bk = (const float*)d_in[9];
    const float* Wv = (const float*)d_in[10], *bv = (const float*)d_in[11];
    const float* Wo = (const float*)d_in[12], *bo = (const float*)d_in[13];
    const float* ln2_g = (const float*)d_in[14], *ln2_b = (const float*)d_in[15];
    const float* Wff = (const float*)d_in[16], *bff = (const float*)d_in[17];
    float* out = (float*)d_out;

    cudaFuncSetAttribute((const void*)gemm_kernel<0,1,0,128>, cudaFuncAttributeMaxDynamicSharedMemorySize, GEMM_SMEM);
    cudaFuncSetAttribute((const void*)gemm_kernel<1,0,1,64>,  cudaFuncAttributeMaxDynamicSharedMemorySize, GEMM_SMEM);
    cudaFuncSetAttribute((const void*)gemm_kernel<1,0,0,64>,  cudaFuncAttributeMaxDynamicSharedMemorySize, GEMM_SMEM);
    cudaFuncSetAttribute((const void*)attn_kernel, cudaFuncAttributeMaxDynamicSharedMemorySize, ATT_SMEM);

    __nv_bfloat16 *xln, *qkv, *cat, *xln2, *wqkv, *wo, *wff;
    float *xout;
    cudaGetSymbolAddress((void**)&xln,  g_xln);
    cudaGetSymbolAddress((void**)&wqkv, g_wqkv);
    cudaGetSymbolAddress((void**)&wo,   g_wo);
    cudaGetSymbolAddress((void**)&wff,  g_wff);
    cudaGetSymbolAddress((void**)&qkv,  g_qkv);
    cudaGetSymbolAddress((void**)&cat,  g_cat);
    cudaGetSymbolAddress((void**)&xout, g_xout);
    cudaGetSymbolAddress((void**)&xln2, g_xln2);

    compact_kernel<<<1, 1024>>>(mask);                                            // 1
    cvt_all_kernel<<<(4*HDD + DIM*DIM)/256, 256>>>(Wq, Wk, Wv, Wo, Wff);          // 2
    ln_kernel<1><<<NTOK, 256>>>(x, ln1_g, ln1_b, xln);                            // 3
    gemm_kernel<0,1,0,128><<<dim3(32,48), 256, GEMM_SMEM>>>(xln, wqkv, DIM,
                                                        bq, bk, bv, nullptr, nullptr, qkv); // 4
    bias_pre_kernel<<<dim3(4, NTOK), 256>>>(spatial, edge);                       // 5
    attn_kernel<<<dim3(NHEAD, NTOK/64), 256, ATT_SMEM>>>();                       // 6 (profiled)
    gemm_kernel<1,0,1,64><<<dim3(64,2), 256, GEMM_SMEM>>>(cat, wo, NHEAD*DIM,
                                                       bo, nullptr, nullptr, x, xout, nullptr);
    ln_kernel<0><<<NTOK, 256>>>(xout, ln2_g, ln2_b, xln2);
    gemm_kernel<1,0,0,64><<<dim3(64,2), 256, GEMM_SMEM>>>(xln2, wff, DIM,
                                                       bff, nullptr, nullptr, xout, out, nullptr);
}